// round 6
// baseline (speedup 1.0000x reference)
#include <cuda_runtime.h>
#include <cuda_bf16.h>
#include <cstdint>

// ---------------------------------------------------------------------------
// Shapes: n1 = n2 = 4096, s = 192, a = 64, d = 256. Split-GEMM K = 768.
// ---------------------------------------------------------------------------
#define N      4096
#define DIM    256
#define SDIM   192
#define ADIM   64
#define KSPLIT 768
#define EPS    1e-8f

// ---------------------------------------------------------------------------
// Scratch (device globals — allocations forbidden)
// ---------------------------------------------------------------------------
__device__ __align__(256) float g_sa [N * DIM];
__device__ __align__(256) float g_esa[N * DIM];
__device__ __align__(256) float g_x2 [N];
__device__ __align__(256) float g_y2 [N];
__device__ __align__(256) float g_D  [(size_t)N * N];       // 64 MB
__device__ __align__(256) float g_D2 [DIM * DIM];
__device__ __align__(256) float g_D2p[8 * DIM * DIM];
__device__ __align__(256) float g_c2part[32 * DIM];
__device__ __align__(256) float g_c2 [DIM];
__device__ __align__(256) float g_sim[N];
__device__ __align__(256) float g_selfpart[(size_t)N * 64]; // 1 MB partial rowsums
__device__ __align__(256) __nv_bfloat16 g_P[(size_t)N * KSPLIT]; // sa  [hi|hi|lo]
__device__ __align__(256) __nv_bfloat16 g_Q[(size_t)N * KSPLIT]; // sa  [hi|lo|hi]
__device__ __align__(256) __nv_bfloat16 g_R[(size_t)N * KSPLIT]; // esa [hi|lo|hi]
__device__ unsigned g_hist[256];     // stays zero between runs (scan clears it)
__device__ unsigned g_prefix;
__device__ unsigned g_k;
__device__ float    g_median[2];
__device__ float    g_gamma[2];

// ---------------------------------------------------------------------------
// helpers
// ---------------------------------------------------------------------------
__device__ __forceinline__ uint32_t smem_u32(const void* p) {
    uint32_t a;
    asm("{ .reg .u64 t; cvta.to.shared.u64 t, %1; cvt.u32.u64 %0, t; }"
        : "=r"(a) : "l"(p));
    return a;
}
#define SW128B(o) ((o) ^ (((o) >> 3) & 0x70))

__device__ __forceinline__ void cp_async16(uint32_t sdst, const void* gsrc) {
    asm volatile("cp.async.cg.shared.global [%0], [%1], 16;"
                 :: "r"(sdst), "l"(gsrc) : "memory");
}
__device__ __forceinline__ void cp_commit() {
    asm volatile("cp.async.commit_group;" ::: "memory");
}
__device__ __forceinline__ void ldmx4(uint32_t& r0, uint32_t& r1,
                                      uint32_t& r2, uint32_t& r3, uint32_t addr) {
    asm volatile("ldmatrix.sync.aligned.m8n8.x4.shared.b16 {%0,%1,%2,%3}, [%4];"
                 : "=r"(r0), "=r"(r1), "=r"(r2), "=r"(r3) : "r"(addr));
}
__device__ __forceinline__ void mma_bf16(float& c0, float& c1, float& c2, float& c3,
                                         uint32_t a0, uint32_t a1, uint32_t a2, uint32_t a3,
                                         uint32_t b0, uint32_t b1) {
    asm volatile(
        "mma.sync.aligned.m16n8k16.row.col.f32.bf16.bf16.f32 "
        "{%0,%1,%2,%3}, {%4,%5,%6,%7}, {%8,%9}, {%0,%1,%2,%3};"
        : "+f"(c0), "+f"(c1), "+f"(c2), "+f"(c3)
        : "r"(a0), "r"(a1), "r"(a2), "r"(a3), "r"(b0), "r"(b1));
}
__device__ __forceinline__ unsigned f2u_mono(float f) {
    unsigned b = __float_as_uint(f);
    return (b & 0x80000000u) ? ~b : (b | 0x80000000u);
}

// ---------------------------------------------------------------------------
// 1) concat + norm + bf16 hi/lo splits, fused (one read of inputs).
//    dst0 layout: phl0=1 -> [hi|hi|lo], phl0=0 -> [hi|lo|hi].
//    dst1 (optional): always [hi|lo|hi].
// ---------------------------------------------------------------------------
__global__ void prep_kernel(const float* __restrict__ st,
                            const float* __restrict__ ac,
                            float* __restrict__ cat, float* __restrict__ nrm,
                            __nv_bfloat16* __restrict__ dst0, int phl0,
                            __nv_bfloat16* __restrict__ dst1) {
    int row = blockIdx.x, t = threadIdx.x;
    float v = (t < SDIM) ? st[row * SDIM + t] : ac[row * ADIM + (t - SDIM)];
    cat[row * DIM + t] = v;
    __nv_bfloat16 hi = __float2bfloat16(v);
    __nv_bfloat16 lo = __float2bfloat16(v - __bfloat162float(hi));
    size_t base = (size_t)row * KSPLIT + t;
    dst0[base]       = hi;
    dst0[base + 256] = phl0 ? hi : lo;
    dst0[base + 512] = phl0 ? lo : hi;
    if (dst1) { dst1[base] = hi; dst1[base + 256] = lo; dst1[base + 512] = hi; }

    __shared__ float sh[256];
    sh[t] = v * v;
    __syncthreads();
    #pragma unroll
    for (int s = 128; s > 0; s >>= 1) {
        if (t < s) sh[t] += sh[t + s];
        __syncthreads();
    }
    if (t == 0) nrm[row] = sh[0];
}

// ---------------------------------------------------------------------------
// 2) HMMA distance GEMM: 256x128 CTA tile, 8 warps (4x2) of 64x64,
//    BK=64, 2-stage cp.async, SW128 smem, K = 768.
//    MODE 0: store D + fused 8-bit MSB histogram into g_hist.
//    MODE 1: fused self-rowsum: partial sums of exp(-g1 d)+exp(-g2 d), no D.
// ---------------------------------------------------------------------------
#define BK        64
#define A_BYTES   (256 * 128)            // 32 KB / stage
#define B_BYTES   (128 * 128)            // 16 KB / stage
#define STAGE_B   (A_BYTES + B_BYTES)    // 48 KB
#define GM_SMEM   (2 * STAGE_B)          // 96 KB
#define NCHUNK    12

__device__ __forceinline__ void gemm_issue_stage(
    const __nv_bfloat16* __restrict__ A, const __nv_bfloat16* __restrict__ B,
    int i0, int j0, int c, uint32_t sA, uint32_t sB, int tid)
{
    const __nv_bfloat16* Ap = A + (size_t)i0 * KSPLIT + c * BK;
    const __nv_bfloat16* Bp = B + (size_t)j0 * KSPLIT + c * BK;
    #pragma unroll
    for (int q = 0; q < 8; q++) {          // A: 256 rows x 8 segs
        int idx = tid + q * 256;
        int row = idx >> 3, seg = idx & 7;
        cp_async16(sA + SW128B(row * 128 + seg * 16),
                   Ap + (size_t)row * KSPLIT + seg * 8);
    }
    #pragma unroll
    for (int q = 0; q < 4; q++) {          // B: 128 rows
        int idx = tid + q * 256;
        int row = idx >> 3, seg = idx & 7;
        cp_async16(sB + SW128B(row * 128 + seg * 16),
                   Bp + (size_t)row * KSPLIT + seg * 8);
    }
    cp_commit();
}

template <int MODE>
__global__ __launch_bounds__(256, 1)
void hmma_dist_gemm(const __nv_bfloat16* __restrict__ A,
                    const __nv_bfloat16* __restrict__ B,
                    const float* __restrict__ x2,
                    const float* __restrict__ y2,
                    float* __restrict__ D)
{
    extern __shared__ char smem[];
    const uint32_t sb = smem_u32(smem);
    const int tid = threadIdx.x;
    const int wid = tid >> 5, lane = tid & 31;
    const int warp_m = wid & 3, warp_n = wid >> 2;   // 4 x 2 warps
    const int i0 = blockIdx.y * 256;
    const int j0 = blockIdx.x * 128;

    uint32_t sA[2] = { sb,           sb + STAGE_B };
    uint32_t sB[2] = { sb + A_BYTES, sb + STAGE_B + A_BYTES };

    float acc[4][8][4];
    #pragma unroll
    for (int mi = 0; mi < 4; mi++)
        #pragma unroll
        for (int ni = 0; ni < 8; ni++)
            #pragma unroll
            for (int e = 0; e < 4; e++) acc[mi][ni][e] = 0.f;

    gemm_issue_stage(A, B, i0, j0, 0, sA[0], sB[0], tid);
    gemm_issue_stage(A, B, i0, j0, 1, sA[1], sB[1], tid);

    const int a_row = (lane & 15);
    const int a_col = (lane & 16) ? 8 : 0;
    const int b_row = (lane & 7) + ((lane & 16) >> 1);
    const int b_col = (lane & 8) ? 8 : 0;

    for (int c = 0; c < NCHUNK; c++) {
        if (c < NCHUNK - 2) asm volatile("cp.async.wait_group 1;" ::: "memory");
        else                asm volatile("cp.async.wait_group 0;" ::: "memory");
        __syncthreads();

        uint32_t cA = sA[c & 1], cB = sB[c & 1];
        #pragma unroll
        for (int ks = 0; ks < BK / 16; ks++) {
            int k0 = ks * 16;
            uint32_t a[4][4], b[4][4];
            #pragma unroll
            for (int mi = 0; mi < 4; mi++) {
                int row = warp_m * 64 + mi * 16 + a_row;
                ldmx4(a[mi][0], a[mi][1], a[mi][2], a[mi][3],
                      cA + SW128B(row * 128 + (k0 + a_col) * 2));
            }
            #pragma unroll
            for (int nb = 0; nb < 4; nb++) {
                int row = warp_n * 64 + nb * 16 + b_row;
                ldmx4(b[nb][0], b[nb][1], b[nb][2], b[nb][3],
                      cB + SW128B(row * 128 + (k0 + b_col) * 2));
            }
            #pragma unroll
            for (int mi = 0; mi < 4; mi++)
                #pragma unroll
                for (int ni = 0; ni < 8; ni++)
                    mma_bf16(acc[mi][ni][0], acc[mi][ni][1],
                             acc[mi][ni][2], acc[mi][ni][3],
                             a[mi][0], a[mi][1], a[mi][2], a[mi][3],
                             b[ni >> 1][(ni & 1) * 2], b[ni >> 1][(ni & 1) * 2 + 1]);
        }
        __syncthreads();
        if (c + 2 < NCHUNK)
            gemm_issue_stage(A, B, i0, j0, c + 2, sA[c & 1], sB[c & 1], tid);
    }

    const int qrow = lane >> 2;            // 0..7
    const int qcol = (lane & 3) * 2;       // 0,2,4,6

    if (MODE == 0) {
        // -------- store D + run-length aggregated MSB histogram --------
        unsigned* hsh = (unsigned*)smem;
        hsh[tid] = 0u;
        __syncthreads();
        unsigned lastb = 0xFFFFFFFFu, cnt = 0;

        #pragma unroll
        for (int mi = 0; mi < 4; mi++) {
            int i_lo = i0 + warp_m * 64 + mi * 16 + qrow;
            int i_hi = i_lo + 8;
            float xlo = x2[i_lo], xhi = x2[i_hi];
            #pragma unroll
            for (int ni = 0; ni < 8; ni++) {
                int j = j0 + warp_n * 64 + ni * 8 + qcol;
                float yj0 = y2[j], yj1 = y2[j + 1];
                float2 vlo, vhi;
                vlo.x = (xlo + yj0 - 2.f * acc[mi][ni][0]) * 0.00390625f;
                vlo.y = (xlo + yj1 - 2.f * acc[mi][ni][1]) * 0.00390625f;
                vhi.x = (xhi + yj0 - 2.f * acc[mi][ni][2]) * 0.00390625f;
                vhi.y = (xhi + yj1 - 2.f * acc[mi][ni][3]) * 0.00390625f;
                *(float2*)(D + (size_t)i_lo * N + j) = vlo;
                *(float2*)(D + (size_t)i_hi * N + j) = vhi;
                float vs[4] = {vlo.x, vlo.y, vhi.x, vhi.y};
                #pragma unroll
                for (int e = 0; e < 4; e++) {
                    unsigned bk = f2u_mono(vs[e]) >> 24;
                    if (bk == lastb) cnt++;
                    else {
                        if (cnt) atomicAdd(&hsh[lastb], cnt);
                        lastb = bk; cnt = 1;
                    }
                }
            }
        }
        if (cnt) atomicAdd(&hsh[lastb], cnt);
        __syncthreads();
        if (hsh[tid]) atomicAdd(&g_hist[tid], hsh[tid]);
    } else {
        // -------- fused self-similarity rowsum (no D materialization) --------
        float g1 = g_gamma[0], g2 = g_gamma[1];
        #pragma unroll
        for (int mi = 0; mi < 4; mi++) {
            int i_lo = i0 + warp_m * 64 + mi * 16 + qrow;
            int i_hi = i_lo + 8;
            float xlo = x2[i_lo], xhi = x2[i_hi];
            float slo = 0.f, shi = 0.f;
            #pragma unroll
            for (int ni = 0; ni < 8; ni++) {
                int j = j0 + warp_n * 64 + ni * 8 + qcol;
                float yj0 = y2[j], yj1 = y2[j + 1];
                float d0 = (xlo + yj0 - 2.f * acc[mi][ni][0]) * 0.00390625f;
                float d1 = (xlo + yj1 - 2.f * acc[mi][ni][1]) * 0.00390625f;
                float d2v = (xhi + yj0 - 2.f * acc[mi][ni][2]) * 0.00390625f;
                float d3 = (xhi + yj1 - 2.f * acc[mi][ni][3]) * 0.00390625f;
                slo += __expf(-g1 * d0) + __expf(-g2 * d0)
                     + __expf(-g1 * d1) + __expf(-g2 * d1);
                shi += __expf(-g1 * d2v) + __expf(-g2 * d2v)
                     + __expf(-g1 * d3) + __expf(-g2 * d3);
            }
            slo += __shfl_xor_sync(0xFFFFFFFFu, slo, 1);
            slo += __shfl_xor_sync(0xFFFFFFFFu, slo, 2);
            shi += __shfl_xor_sync(0xFFFFFFFFu, shi, 1);
            shi += __shfl_xor_sync(0xFFFFFFFFu, shi, 2);
            if ((lane & 3) == 0) {
                int col = blockIdx.x * 2 + warp_n;      // 0..63
                g_selfpart[(size_t)i_lo * 64 + col] = slo;
                g_selfpart[(size_t)i_hi * 64 + col] = shi;
            }
        }
    }
}

// ---------------------------------------------------------------------------
// 3) gamma_2 path
// ---------------------------------------------------------------------------
__global__ void colnorm_part_kernel() {
    int b = blockIdx.x, t = threadIdx.x;
    float s = 0.f;
    int r0 = b * 128;
    for (int r = 0; r < 128; r++) {
        float v = g_esa[(size_t)(r0 + r) * DIM + t];
        s += v * v;
    }
    g_c2part[b * DIM + t] = s;
}
__global__ void colnorm_reduce_kernel() {
    int t = threadIdx.x;
    float s = 0.f;
    for (int b = 0; b < 32; b++) s += g_c2part[b * DIM + t];
    g_c2[t] = s;
}
__global__ __launch_bounds__(256)
void d2_part_kernel() {
    __shared__ float Ei[64][32];
    __shared__ float Ej[64][32];
    const int tx = threadIdx.x & 15, ty = threadIdx.x >> 4;
    const int i0 = blockIdx.y * 32, j0 = blockIdx.x * 32;
    const int k0 = blockIdx.z * 512;
    float a00 = 0, a01 = 0, a10 = 0, a11 = 0;
    for (int kc = k0; kc < k0 + 512; kc += 64) {
        #pragma unroll
        for (int r = 0; r < 8; r++) {
            int idx = threadIdx.x + r * 256;
            int kk = idx >> 5, col = idx & 31;
            Ei[kk][col] = g_esa[(size_t)(kc + kk) * DIM + i0 + col];
            Ej[kk][col] = g_esa[(size_t)(kc + kk) * DIM + j0 + col];
        }
        __syncthreads();
        #pragma unroll
        for (int kk = 0; kk < 64; kk++) {
            float xa = Ei[kk][ty], xb = Ei[kk][ty + 16];
            float ya = Ej[kk][tx], yb = Ej[kk][tx + 16];
            a00 += xa * ya; a01 += xa * yb; a10 += xb * ya; a11 += xb * yb;
        }
        __syncthreads();
    }
    float* P = g_D2p + (size_t)blockIdx.z * DIM * DIM;
    P[(i0 + ty) * DIM + j0 + tx]           = a00;
    P[(i0 + ty) * DIM + j0 + tx + 16]      = a01;
    P[(i0 + ty + 16) * DIM + j0 + tx]      = a10;
    P[(i0 + ty + 16) * DIM + j0 + tx + 16] = a11;
}
__global__ void d2_final_kernel() {
    int i = blockIdx.x, j = threadIdx.x;
    float s = 0.f;
    #pragma unroll
    for (int z = 0; z < 8; z++) s += g_D2p[(size_t)z * DIM * DIM + i * DIM + j];
    g_D2[i * DIM + j] = (g_c2[i] + g_c2[j] - 2.f * s) * (1.f / 4096.f);
}

// ---------------------------------------------------------------------------
// 4) radix select
// ---------------------------------------------------------------------------
__global__ void select_init_kernel(unsigned k) {   // full init (zeroes hist)
    if (threadIdx.x == 0) { g_prefix = 0u; g_k = k; }
    g_hist[threadIdx.x] = 0u;
}
__global__ void select_setpk_kernel(unsigned k) {  // keep fused histogram
    g_prefix = 0u; g_k = k;
}
__global__ void select_hist_kernel(const float* __restrict__ data, unsigned n4, int shift) {
    __shared__ unsigned sh[256];
    sh[threadIdx.x] = 0u;
    __syncthreads();
    unsigned prefix = g_prefix;
    unsigned stride = gridDim.x * blockDim.x;
    int lane = threadIdx.x & 31;
    const float4* d4 = (const float4*)data;
    for (unsigned base = blockIdx.x * blockDim.x; base < n4; base += stride) {
        unsigned i = base + threadIdx.x;
        float4 v = make_float4(0.f, 0.f, 0.f, 0.f);
        bool valid = (i < n4);
        if (valid) v = d4[i];
        float vals[4] = {v.x, v.y, v.z, v.w};
        #pragma unroll
        for (int e = 0; e < 4; e++) {
            unsigned bucket = 0xFFFFFFFFu;
            if (valid) {
                unsigned u = f2u_mono(vals[e]);
                bool ok = (shift == 24) || ((u >> (shift + 8)) == prefix);
                if (ok) bucket = (u >> shift) & 0xFFu;
            }
            unsigned m = __match_any_sync(0xFFFFFFFFu, bucket);
            if (bucket != 0xFFFFFFFFu && lane == __ffs(m) - 1)
                atomicAdd(&sh[bucket], (unsigned)__popc(m));
        }
    }
    __syncthreads();
    if (sh[threadIdx.x]) atomicAdd(&g_hist[threadIdx.x], sh[threadIdx.x]);
}
__global__ void select_scan_kernel() {
    __shared__ unsigned s[256];
    int t = threadIdx.x;
    unsigned c = g_hist[t];
    s[t] = c;
    __syncthreads();
    for (int off = 1; off < 256; off <<= 1) {
        unsigned v = (t >= off) ? s[t - off] : 0u;
        __syncthreads();
        s[t] += v;
        __syncthreads();
    }
    unsigned k = g_k;
    unsigned incl = s[t], excl = incl - c;
    if (k >= excl && k < incl) {
        g_k = k - excl;
        g_prefix = (g_prefix << 8) | (unsigned)t;
    }
    g_hist[t] = 0u;
}
__global__ void select_finalize_kernel(int idx) {
    unsigned u = g_prefix;
    unsigned bits = (u & 0x80000000u) ? (u ^ 0x80000000u) : ~u;
    g_median[idx] = __uint_as_float(bits);
}
__global__ void gamma_kernel() {
    g_gamma[0] = 1.0f / (g_median[0] + EPS);
    g_gamma[1] = 1.0f / (g_median[1] + EPS);
}

// ---------------------------------------------------------------------------
// 5) Row means of exp(-g1*D) + exp(-g2*D) over stored D (agent-expert pass)
// ---------------------------------------------------------------------------
__global__ __launch_bounds__(256)
void rowsum_kernel(const float* __restrict__ D) {
    int i = blockIdx.x, t = threadIdx.x;
    float g1 = g_gamma[0], g2 = g_gamma[1];
    const float4* row = (const float4*)(D + (size_t)i * N);
    float s = 0.f;
    #pragma unroll 4
    for (int j = t; j < N / 4; j += 256) {
        float4 v = row[j];
        s += __expf(-g1 * v.x) + __expf(-g1 * v.y) + __expf(-g1 * v.z) + __expf(-g1 * v.w)
           + __expf(-g2 * v.x) + __expf(-g2 * v.y) + __expf(-g2 * v.z) + __expf(-g2 * v.w);
    }
    __shared__ float sh[256];
    sh[t] = s;
    __syncthreads();
    #pragma unroll
    for (int k = 128; k > 0; k >>= 1) {
        if (t < k) sh[t] += sh[t + k];
        __syncthreads();
    }
    if (t == 0) g_sim[i] = sh[0] * (1.0f / (float)N);
}

// ---------------------------------------------------------------------------
// 6) final: out[i] = g_sim[i] - mean(selfpart[i])
// ---------------------------------------------------------------------------
__global__ void self_final_kernel(float* __restrict__ out) {
    int i = blockIdx.x * blockDim.x + threadIdx.x;
    const float4* p = (const float4*)(g_selfpart + (size_t)i * 64);
    float s = 0.f;
    #pragma unroll
    for (int b = 0; b < 16; b++) {
        float4 v = p[b];
        s += v.x + v.y + v.z + v.w;
    }
    out[i] = g_sim[i] - s * (1.0f / (float)N);
}

// ---------------------------------------------------------------------------
// Host orchestration (graph-capturable)
// ---------------------------------------------------------------------------
extern "C" void kernel_launch(void* const* d_in, const int* in_sizes, int n_in,
                              void* d_out, int out_size) {
    const float* state   = (const float*)d_in[0];
    const float* action  = (const float*)d_in[1];
    const float* estate  = (const float*)d_in[2];
    const float* eaction = (const float*)d_in[3];
    float* out = (float*)d_out;

    float *p_sa, *p_esa, *p_x2, *p_y2, *p_D, *p_D2;
    __nv_bfloat16 *p_P, *p_Q, *p_R;
    cudaGetSymbolAddress((void**)&p_sa,  g_sa);
    cudaGetSymbolAddress((void**)&p_esa, g_esa);
    cudaGetSymbolAddress((void**)&p_x2,  g_x2);
    cudaGetSymbolAddress((void**)&p_y2,  g_y2);
    cudaGetSymbolAddress((void**)&p_D,   g_D);
    cudaGetSymbolAddress((void**)&p_D2,  g_D2);
    cudaGetSymbolAddress((void**)&p_P,   g_P);
    cudaGetSymbolAddress((void**)&p_Q,   g_Q);
    cudaGetSymbolAddress((void**)&p_R,   g_R);

    cudaFuncSetAttribute(hmma_dist_gemm<0>,
                         cudaFuncAttributeMaxDynamicSharedMemorySize, GM_SMEM);
    cudaFuncSetAttribute(hmma_dist_gemm<1>,
                         cudaFuncAttributeMaxDynamicSharedMemorySize, GM_SMEM);

    // 1) concat + norms + bf16 splits (fused; expert MUST be [hi|lo|hi])
    prep_kernel<<<N, 256>>>(state,  action,  p_sa,  p_x2, p_P, 1, p_Q);
    prep_kernel<<<N, 256>>>(estate, eaction, p_esa, p_y2, p_R, 0, nullptr);

    // 2) D_agent_expert + fused MSB histogram (g_hist starts/ends zero)
    dim3 ggrid(N / 128, N / 256);
    hmma_dist_gemm<0><<<ggrid, 256, GM_SMEM>>>(p_P, p_R, p_x2, p_y2, p_D);

    // 3) gamma_2 small distance matrix
    colnorm_part_kernel<<<32, 256>>>();
    colnorm_reduce_kernel<<<1, 256>>>();
    d2_part_kernel<<<dim3(8, 8, 8), 256>>>();
    d2_final_kernel<<<DIM, DIM>>>();

    // 4a) median of D: pass 1 came from the fused histogram
    {
        unsigned n = (unsigned)N * (unsigned)N;
        unsigned n4 = n / 4;
        unsigned blocks = (n4 + 255u) / 256u;
        if (blocks > 2048u) blocks = 2048u;
        select_setpk_kernel<<<1, 1>>>((n - 1u) / 2u);
        select_scan_kernel<<<1, 256>>>();                 // consume fused hist
        const int shifts[3] = {16, 8, 0};
        for (int p = 0; p < 3; p++) {
            select_hist_kernel<<<blocks, 256>>>(p_D, n4, shifts[p]);
            select_scan_kernel<<<1, 256>>>();
        }
        select_finalize_kernel<<<1, 1>>>(0);
    }
    // 4b) median of D2 (full 4-pass, tiny)
    {
        unsigned n = (unsigned)(DIM * DIM), n4 = n / 4;
        unsigned blocks = (n4 + 255u) / 256u;
        select_init_kernel<<<1, 256>>>((n - 1u) / 2u);
        const int shifts[4] = {24, 16, 8, 0};
        for (int p = 0; p < 4; p++) {
            select_hist_kernel<<<blocks, 256>>>(p_D2, n4, shifts[p]);
            select_scan_kernel<<<1, 256>>>();
        }
        select_finalize_kernel<<<1, 1>>>(1);
    }
    gamma_kernel<<<1, 1>>>();

    // 5) agent-expert similarity means from stored D
    rowsum_kernel<<<N, 256>>>(p_D);

    // 6) self-distance GEMM with fused rowsum (no D materialization)
    hmma_dist_gemm<1><<<ggrid, 256, GM_SMEM>>>(p_P, p_Q, p_x2, p_x2, nullptr);
    self_final_kernel<<<N / 256, 256>>>(out);
}

// round 7
// speedup vs baseline: 1.4415x; 1.4415x over previous
#include <cuda_runtime.h>
#include <cuda_bf16.h>
#include <cstdint>

// ---------------------------------------------------------------------------
// Shapes: n1 = n2 = 4096, s = 192, a = 64, d = 256. Split-GEMM K = 768.
// ---------------------------------------------------------------------------
#define N      4096
#define DIM    256
#define SDIM   192
#define ADIM   64
#define KSPLIT 768
#define EPS    1e-8f

// ---------------------------------------------------------------------------
// Scratch (device globals — allocations forbidden)
// ---------------------------------------------------------------------------
__device__ __align__(256) float g_sa [N * DIM];
__device__ __align__(256) float g_esa[N * DIM];
__device__ __align__(256) float g_x2 [N];
__device__ __align__(256) float g_y2 [N];
__device__ __align__(256) float g_D  [(size_t)N * N];        // 64 MB
__device__ __align__(256) float g_D2 [DIM * DIM];
__device__ __align__(256) float g_D2p[8 * DIM * DIM];
__device__ __align__(256) float g_c2part[32 * DIM];
__device__ __align__(256) float g_c2 [DIM];
__device__ __align__(256) float g_sim[N];
__device__ __align__(256) float g_selfpart[(size_t)N * 128]; // 2 MB partial rowsums
__device__ __align__(256) __nv_bfloat16 g_P[(size_t)N * KSPLIT]; // sa  [hi|hi|lo]
__device__ __align__(256) __nv_bfloat16 g_Q[(size_t)N * KSPLIT]; // sa  [hi|lo|hi]
__device__ __align__(256) __nv_bfloat16 g_R[(size_t)N * KSPLIT]; // esa [hi|lo|hi]
__device__ unsigned g_hist[256];   // zero at start; scan re-zeroes after use
__device__ unsigned g_prefix;
__device__ unsigned g_k;
__device__ float    g_median[2];
__device__ float    g_gamma[2];

// ---------------------------------------------------------------------------
// helpers
// ---------------------------------------------------------------------------
__device__ __forceinline__ uint32_t smem_u32(const void* p) {
    uint32_t a;
    asm("{ .reg .u64 t; cvta.to.shared.u64 t, %1; cvt.u32.u64 %0, t; }"
        : "=r"(a) : "l"(p));
    return a;
}
#define SW128B(o) ((o) ^ (((o) >> 3) & 0x70))

__device__ __forceinline__ void cp_async16(uint32_t sdst, const void* gsrc) {
    asm volatile("cp.async.cg.shared.global [%0], [%1], 16;"
                 :: "r"(sdst), "l"(gsrc) : "memory");
}
__device__ __forceinline__ void cp_commit() {
    asm volatile("cp.async.commit_group;" ::: "memory");
}
__device__ __forceinline__ void ldmx4(uint32_t& r0, uint32_t& r1,
                                      uint32_t& r2, uint32_t& r3, uint32_t addr) {
    asm volatile("ldmatrix.sync.aligned.m8n8.x4.shared.b16 {%0,%1,%2,%3}, [%4];"
                 : "=r"(r0), "=r"(r1), "=r"(r2), "=r"(r3) : "r"(addr));
}
__device__ __forceinline__ void mma_bf16(float& c0, float& c1, float& c2, float& c3,
                                         uint32_t a0, uint32_t a1, uint32_t a2, uint32_t a3,
                                         uint32_t b0, uint32_t b1) {
    asm volatile(
        "mma.sync.aligned.m16n8k16.row.col.f32.bf16.bf16.f32 "
        "{%0,%1,%2,%3}, {%4,%5,%6,%7}, {%8,%9}, {%0,%1,%2,%3};"
        : "+f"(c0), "+f"(c1), "+f"(c2), "+f"(c3)
        : "r"(a0), "r"(a1), "r"(a2), "r"(a3), "r"(b0), "r"(b1));
}
__device__ __forceinline__ unsigned f2u_mono(float f) {
    unsigned b = __float_as_uint(f);
    return (b & 0x80000000u) ? ~b : (b | 0x80000000u);
}

// ---------------------------------------------------------------------------
// 1) concat + norm + bf16 hi/lo splits, fused.
//    dst0: phl0=1 -> [hi|hi|lo], phl0=0 -> [hi|lo|hi]. dst1: always [hi|lo|hi].
// ---------------------------------------------------------------------------
__global__ void prep_kernel(const float* __restrict__ st,
                            const float* __restrict__ ac,
                            float* __restrict__ cat, float* __restrict__ nrm,
                            __nv_bfloat16* __restrict__ dst0, int phl0,
                            __nv_bfloat16* __restrict__ dst1) {
    int row = blockIdx.x, t = threadIdx.x;
    float v = (t < SDIM) ? st[row * SDIM + t] : ac[row * ADIM + (t - SDIM)];
    cat[row * DIM + t] = v;
    __nv_bfloat16 hi = __float2bfloat16(v);
    __nv_bfloat16 lo = __float2bfloat16(v - __bfloat162float(hi));
    size_t base = (size_t)row * KSPLIT + t;
    dst0[base]       = hi;
    dst0[base + 256] = phl0 ? hi : lo;
    dst0[base + 512] = phl0 ? lo : hi;
    if (dst1) { dst1[base] = hi; dst1[base + 256] = lo; dst1[base + 512] = hi; }

    __shared__ float sh[256];
    sh[t] = v * v;
    __syncthreads();
    #pragma unroll
    for (int s = 128; s > 0; s >>= 1) {
        if (t < s) sh[t] += sh[t + s];
        __syncthreads();
    }
    if (t == 0) nrm[row] = sh[0];
}

// ---------------------------------------------------------------------------
// 2) HMMA distance GEMM — R3 geometry (proven): 128x128 CTA tile, 8 warps
//    (2x4) of 64x32, BK=64, 2-stage cp.async, SW128 smem, K = 768.
//    MODE 0: store D + fused MSB histogram.   MODE 1: fused self-rowsum.
// ---------------------------------------------------------------------------
#define BK        64
#define TILE_B    (128 * BK * 2)          // 16 KB per operand per stage
#define GM_SMEM   (4 * TILE_B)            // 64 KB
#define NCHUNK    12

__device__ __forceinline__ void gemm_issue_stage(
    const __nv_bfloat16* __restrict__ A, const __nv_bfloat16* __restrict__ B,
    int i0, int j0, int c, uint32_t sA, uint32_t sB, int tid)
{
    const __nv_bfloat16* Ap = A + (size_t)i0 * KSPLIT + c * BK;
    const __nv_bfloat16* Bp = B + (size_t)j0 * KSPLIT + c * BK;
    #pragma unroll
    for (int q = 0; q < 4; q++) {
        int idx = tid + q * 256;
        int row = idx >> 3, seg = idx & 7;
        cp_async16(sA + SW128B(row * 128 + seg * 16),
                   Ap + (size_t)row * KSPLIT + seg * 8);
    }
    #pragma unroll
    for (int q = 0; q < 4; q++) {
        int idx = tid + q * 256;
        int row = idx >> 3, seg = idx & 7;
        cp_async16(sB + SW128B(row * 128 + seg * 16),
                   Bp + (size_t)row * KSPLIT + seg * 8);
    }
    cp_commit();
}

template <int MODE>
__global__ __launch_bounds__(256, 1)
void hmma_dist_gemm(const __nv_bfloat16* __restrict__ A,
                    const __nv_bfloat16* __restrict__ B,
                    const float* __restrict__ x2,
                    const float* __restrict__ y2,
                    float* __restrict__ D)
{
    extern __shared__ char smem[];
    const uint32_t sb = smem_u32(smem);
    const int tid = threadIdx.x;
    const int wid = tid >> 5, lane = tid & 31;
    const int warp_m = wid >> 2, warp_n = wid & 3;   // 2 x 4 warps
    const int i0 = blockIdx.y * 128;
    const int j0 = blockIdx.x * 128;

    uint32_t sA[2] = { sb,          sb + 2 * TILE_B };
    uint32_t sB[2] = { sb + TILE_B, sb + 3 * TILE_B };

    float acc[4][4][4];
    #pragma unroll
    for (int mi = 0; mi < 4; mi++)
        #pragma unroll
        for (int ni = 0; ni < 4; ni++)
            #pragma unroll
            for (int e = 0; e < 4; e++) acc[mi][ni][e] = 0.f;

    gemm_issue_stage(A, B, i0, j0, 0, sA[0], sB[0], tid);
    gemm_issue_stage(A, B, i0, j0, 1, sA[1], sB[1], tid);

    const int a_row = (lane & 15);
    const int a_col = (lane & 16) ? 8 : 0;
    const int b_row = (lane & 7) + ((lane & 16) >> 1);
    const int b_col = (lane & 8) ? 8 : 0;

    for (int c = 0; c < NCHUNK; c++) {
        if (c < NCHUNK - 2) asm volatile("cp.async.wait_group 1;" ::: "memory");
        else                asm volatile("cp.async.wait_group 0;" ::: "memory");
        __syncthreads();

        uint32_t cA = sA[c & 1], cB = sB[c & 1];
        #pragma unroll
        for (int ks = 0; ks < BK / 16; ks++) {
            int k0 = ks * 16;
            uint32_t a[4][4], b[2][4];
            #pragma unroll
            for (int mi = 0; mi < 4; mi++) {
                int row = warp_m * 64 + mi * 16 + a_row;
                ldmx4(a[mi][0], a[mi][1], a[mi][2], a[mi][3],
                      cA + SW128B(row * 128 + (k0 + a_col) * 2));
            }
            #pragma unroll
            for (int nb = 0; nb < 2; nb++) {
                int row = warp_n * 32 + nb * 16 + b_row;
                ldmx4(b[nb][0], b[nb][1], b[nb][2], b[nb][3],
                      cB + SW128B(row * 128 + (k0 + b_col) * 2));
            }
            #pragma unroll
            for (int mi = 0; mi < 4; mi++)
                #pragma unroll
                for (int ni = 0; ni < 4; ni++)
                    mma_bf16(acc[mi][ni][0], acc[mi][ni][1],
                             acc[mi][ni][2], acc[mi][ni][3],
                             a[mi][0], a[mi][1], a[mi][2], a[mi][3],
                             b[ni >> 1][(ni & 1) * 2], b[ni >> 1][(ni & 1) * 2 + 1]);
        }
        __syncthreads();
        if (c + 2 < NCHUNK)
            gemm_issue_stage(A, B, i0, j0, c + 2, sA[c & 1], sB[c & 1], tid);
    }

    const int qrow = lane >> 2;            // 0..7
    const int qcol = (lane & 3) * 2;       // 0,2,4,6

    if (MODE == 0) {
        // -------- store D + run-length aggregated MSB histogram --------
        unsigned* hsh = (unsigned*)smem;
        hsh[tid] = 0u;
        __syncthreads();
        unsigned lastb = 0xFFFFFFFFu, cnt = 0;

        #pragma unroll
        for (int mi = 0; mi < 4; mi++) {
            int i_lo = i0 + warp_m * 64 + mi * 16 + qrow;
            int i_hi = i_lo + 8;
            float xlo = x2[i_lo], xhi = x2[i_hi];
            #pragma unroll
            for (int ni = 0; ni < 4; ni++) {
                int j = j0 + warp_n * 32 + ni * 8 + qcol;
                float yj0 = y2[j], yj1 = y2[j + 1];
                float2 vlo, vhi;
                vlo.x = (xlo + yj0 - 2.f * acc[mi][ni][0]) * 0.00390625f;
                vlo.y = (xlo + yj1 - 2.f * acc[mi][ni][1]) * 0.00390625f;
                vhi.x = (xhi + yj0 - 2.f * acc[mi][ni][2]) * 0.00390625f;
                vhi.y = (xhi + yj1 - 2.f * acc[mi][ni][3]) * 0.00390625f;
                *(float2*)(D + (size_t)i_lo * N + j) = vlo;
                *(float2*)(D + (size_t)i_hi * N + j) = vhi;
                float vs[4] = {vlo.x, vlo.y, vhi.x, vhi.y};
                #pragma unroll
                for (int e = 0; e < 4; e++) {
                    unsigned bk = f2u_mono(vs[e]) >> 24;
                    if (bk == lastb) cnt++;
                    else {
                        if (cnt) atomicAdd(&hsh[lastb], cnt);
                        lastb = bk; cnt = 1;
                    }
                }
            }
        }
        if (cnt) atomicAdd(&hsh[lastb], cnt);
        __syncthreads();
        if (hsh[tid]) atomicAdd(&g_hist[tid], hsh[tid]);
    } else {
        // -------- fused self-similarity rowsum (no D materialization) --------
        float g1 = g_gamma[0], g2 = g_gamma[1];
        #pragma unroll
        for (int mi = 0; mi < 4; mi++) {
            int i_lo = i0 + warp_m * 64 + mi * 16 + qrow;
            int i_hi = i_lo + 8;
            float xlo = x2[i_lo], xhi = x2[i_hi];
            float slo = 0.f, shi = 0.f;
            #pragma unroll
            for (int ni = 0; ni < 4; ni++) {
                int j = j0 + warp_n * 32 + ni * 8 + qcol;
                float yj0 = y2[j], yj1 = y2[j + 1];
                float d0 = (xlo + yj0 - 2.f * acc[mi][ni][0]) * 0.00390625f;
                float d1 = (xlo + yj1 - 2.f * acc[mi][ni][1]) * 0.00390625f;
                float d2v = (xhi + yj0 - 2.f * acc[mi][ni][2]) * 0.00390625f;
                float d3 = (xhi + yj1 - 2.f * acc[mi][ni][3]) * 0.00390625f;
                slo += __expf(-g1 * d0) + __expf(-g2 * d0)
                     + __expf(-g1 * d1) + __expf(-g2 * d1);
                shi += __expf(-g1 * d2v) + __expf(-g2 * d2v)
                     + __expf(-g1 * d3) + __expf(-g2 * d3);
            }
            slo += __shfl_xor_sync(0xFFFFFFFFu, slo, 1);
            slo += __shfl_xor_sync(0xFFFFFFFFu, slo, 2);
            shi += __shfl_xor_sync(0xFFFFFFFFu, shi, 1);
            shi += __shfl_xor_sync(0xFFFFFFFFu, shi, 2);
            if ((lane & 3) == 0) {
                int col = blockIdx.x * 4 + warp_n;      // 0..127
                g_selfpart[(size_t)i_lo * 128 + col] = slo;
                g_selfpart[(size_t)i_hi * 128 + col] = shi;
            }
        }
    }
}

// ---------------------------------------------------------------------------
// 3) gamma_2 path
// ---------------------------------------------------------------------------
__global__ void colnorm_part_kernel() {
    int b = blockIdx.x, t = threadIdx.x;
    float s = 0.f;
    int r0 = b * 128;
    for (int r = 0; r < 128; r++) {
        float v = g_esa[(size_t)(r0 + r) * DIM + t];
        s += v * v;
    }
    g_c2part[b * DIM + t] = s;
}
__global__ void colnorm_reduce_kernel() {
    int t = threadIdx.x;
    float s = 0.f;
    for (int b = 0; b < 32; b++) s += g_c2part[b * DIM + t];
    g_c2[t] = s;
}
__global__ __launch_bounds__(256)
void d2_part_kernel() {
    __shared__ float Ei[64][32];
    __shared__ float Ej[64][32];
    const int tx = threadIdx.x & 15, ty = threadIdx.x >> 4;
    const int i0 = blockIdx.y * 32, j0 = blockIdx.x * 32;
    const int k0 = blockIdx.z * 512;
    float a00 = 0, a01 = 0, a10 = 0, a11 = 0;
    for (int kc = k0; kc < k0 + 512; kc += 64) {
        #pragma unroll
        for (int r = 0; r < 8; r++) {
            int idx = threadIdx.x + r * 256;
            int kk = idx >> 5, col = idx & 31;
            Ei[kk][col] = g_esa[(size_t)(kc + kk) * DIM + i0 + col];
            Ej[kk][col] = g_esa[(size_t)(kc + kk) * DIM + j0 + col];
        }
        __syncthreads();
        #pragma unroll
        for (int kk = 0; kk < 64; kk++) {
            float xa = Ei[kk][ty], xb = Ei[kk][ty + 16];
            float ya = Ej[kk][tx], yb = Ej[kk][tx + 16];
            a00 += xa * ya; a01 += xa * yb; a10 += xb * ya; a11 += xb * yb;
        }
        __syncthreads();
    }
    float* P = g_D2p + (size_t)blockIdx.z * DIM * DIM;
    P[(i0 + ty) * DIM + j0 + tx]           = a00;
    P[(i0 + ty) * DIM + j0 + tx + 16]      = a01;
    P[(i0 + ty + 16) * DIM + j0 + tx]      = a10;
    P[(i0 + ty + 16) * DIM + j0 + tx + 16] = a11;
}
__global__ void d2_final_kernel() {
    int i = blockIdx.x, j = threadIdx.x;
    float s = 0.f;
    #pragma unroll
    for (int z = 0; z < 8; z++) s += g_D2p[(size_t)z * DIM * DIM + i * DIM + j];
    g_D2[i * DIM + j] = (g_c2[i] + g_c2[j] - 2.f * s) * (1.f / 4096.f);
}

// ---------------------------------------------------------------------------
// 4) radix select
// ---------------------------------------------------------------------------
__global__ void select_init_kernel(unsigned k) {
    if (threadIdx.x == 0) { g_prefix = 0u; g_k = k; }
    g_hist[threadIdx.x] = 0u;
}
__global__ void select_setpk_kernel(unsigned k) {
    g_prefix = 0u; g_k = k;
}
__global__ void select_hist_kernel(const float* __restrict__ data, unsigned n4, int shift) {
    __shared__ unsigned sh[256];
    sh[threadIdx.x] = 0u;
    __syncthreads();
    unsigned prefix = g_prefix;
    unsigned stride = gridDim.x * blockDim.x;
    int lane = threadIdx.x & 31;
    const float4* d4 = (const float4*)data;
    for (unsigned base = blockIdx.x * blockDim.x; base < n4; base += stride) {
        unsigned i = base + threadIdx.x;
        float4 v = make_float4(0.f, 0.f, 0.f, 0.f);
        bool valid = (i < n4);
        if (valid) v = d4[i];
        float vals[4] = {v.x, v.y, v.z, v.w};
        #pragma unroll
        for (int e = 0; e < 4; e++) {
            unsigned bucket = 0xFFFFFFFFu;
            if (valid) {
                unsigned u = f2u_mono(vals[e]);
                bool ok = (shift == 24) || ((u >> (shift + 8)) == prefix);
                if (ok) bucket = (u >> shift) & 0xFFu;
            }
            unsigned m = __match_any_sync(0xFFFFFFFFu, bucket);
            if (bucket != 0xFFFFFFFFu && lane == __ffs(m) - 1)
                atomicAdd(&sh[bucket], (unsigned)__popc(m));
        }
    }
    __syncthreads();
    if (sh[threadIdx.x]) atomicAdd(&g_hist[threadIdx.x], sh[threadIdx.x]);
}
__global__ void select_scan_kernel() {
    __shared__ unsigned s[256];
    int t = threadIdx.x;
    unsigned c = g_hist[t];
    s[t] = c;
    __syncthreads();
    for (int off = 1; off < 256; off <<= 1) {
        unsigned v = (t >= off) ? s[t - off] : 0u;
        __syncthreads();
        s[t] += v;
        __syncthreads();
    }
    unsigned k = g_k;
    unsigned incl = s[t], excl = incl - c;
    if (k >= excl && k < incl) {
        g_k = k - excl;
        g_prefix = (g_prefix << 8) | (unsigned)t;
    }
    g_hist[t] = 0u;
}
__global__ void select_finalize_kernel(int idx) {
    unsigned u = g_prefix;
    unsigned bits = (u & 0x80000000u) ? (u ^ 0x80000000u) : ~u;
    g_median[idx] = __uint_as_float(bits);
}
__global__ void gamma_kernel() {
    g_gamma[0] = 1.0f / (g_median[0] + EPS);
    g_gamma[1] = 1.0f / (g_median[1] + EPS);
}

// ---------------------------------------------------------------------------
// 5) Row means of exp over stored D (agent-expert pass)
// ---------------------------------------------------------------------------
__global__ __launch_bounds__(256)
void rowsum_kernel(const float* __restrict__ D) {
    int i = blockIdx.x, t = threadIdx.x;
    float g1 = g_gamma[0], g2 = g_gamma[1];
    const float4* row = (const float4*)(D + (size_t)i * N);
    float s = 0.f;
    #pragma unroll 4
    for (int j = t; j < N / 4; j += 256) {
        float4 v = row[j];
        s += __expf(-g1 * v.x) + __expf(-g1 * v.y) + __expf(-g1 * v.z) + __expf(-g1 * v.w)
           + __expf(-g2 * v.x) + __expf(-g2 * v.y) + __expf(-g2 * v.z) + __expf(-g2 * v.w);
    }
    __shared__ float sh[256];
    sh[t] = s;
    __syncthreads();
    #pragma unroll
    for (int k = 128; k > 0; k >>= 1) {
        if (t < k) sh[t] += sh[t + k];
        __syncthreads();
    }
    if (t == 0) g_sim[i] = sh[0] * (1.0f / (float)N);
}

// ---------------------------------------------------------------------------
// 6) final: out[i] = g_sim[i] - mean(selfpart[i])
// ---------------------------------------------------------------------------
__global__ void self_final_kernel(float* __restrict__ out) {
    int i = blockIdx.x * blockDim.x + threadIdx.x;
    const float4* p = (const float4*)(g_selfpart + (size_t)i * 128);
    float s = 0.f;
    #pragma unroll
    for (int b = 0; b < 32; b++) {
        float4 v = p[b];
        s += v.x + v.y + v.z + v.w;
    }
    out[i] = g_sim[i] - s * (1.0f / (float)N);
}

// ---------------------------------------------------------------------------
// Host orchestration (graph-capturable)
// ---------------------------------------------------------------------------
extern "C" void kernel_launch(void* const* d_in, const int* in_sizes, int n_in,
                              void* d_out, int out_size) {
    const float* state   = (const float*)d_in[0];
    const float* action  = (const float*)d_in[1];
    const float* estate  = (const float*)d_in[2];
    const float* eaction = (const float*)d_in[3];
    float* out = (float*)d_out;

    float *p_sa, *p_esa, *p_x2, *p_y2, *p_D, *p_D2;
    __nv_bfloat16 *p_P, *p_Q, *p_R;
    cudaGetSymbolAddress((void**)&p_sa,  g_sa);
    cudaGetSymbolAddress((void**)&p_esa, g_esa);
    cudaGetSymbolAddress((void**)&p_x2,  g_x2);
    cudaGetSymbolAddress((void**)&p_y2,  g_y2);
    cudaGetSymbolAddress((void**)&p_D,   g_D);
    cudaGetSymbolAddress((void**)&p_D2,  g_D2);
    cudaGetSymbolAddress((void**)&p_P,   g_P);
    cudaGetSymbolAddress((void**)&p_Q,   g_Q);
    cudaGetSymbolAddress((void**)&p_R,   g_R);

    cudaFuncSetAttribute(hmma_dist_gemm<0>,
                         cudaFuncAttributeMaxDynamicSharedMemorySize, GM_SMEM);
    cudaFuncSetAttribute(hmma_dist_gemm<1>,
                         cudaFuncAttributeMaxDynamicSharedMemorySize, GM_SMEM);

    // 1) concat + norms + bf16 splits (fused; expert MUST be [hi|lo|hi])
    prep_kernel<<<N, 256>>>(state,  action,  p_sa,  p_x2, p_P, 1, p_Q);
    prep_kernel<<<N, 256>>>(estate, eaction, p_esa, p_y2, p_R, 0, nullptr);

    // 2) D_agent_expert + fused MSB histogram
    dim3 ggrid(N / 128, N / 128);
    hmma_dist_gemm<0><<<ggrid, 256, GM_SMEM>>>(p_P, p_R, p_x2, p_y2, p_D);

    // 3) gamma_2 small distance matrix
    colnorm_part_kernel<<<32, 256>>>();
    colnorm_reduce_kernel<<<1, 256>>>();
    d2_part_kernel<<<dim3(8, 8, 8), 256>>>();
    d2_final_kernel<<<DIM, DIM>>>();

    // 4a) median of D: pass 1 from the fused histogram
    {
        unsigned n = (unsigned)N * (unsigned)N;
        unsigned n4 = n / 4;
        unsigned blocks = (n4 + 255u) / 256u;
        if (blocks > 2048u) blocks = 2048u;
        select_setpk_kernel<<<1, 1>>>((n - 1u) / 2u);
        select_scan_kernel<<<1, 256>>>();                 // consume fused hist
        const int shifts[3] = {16, 8, 0};
        for (int p = 0; p < 3; p++) {
            select_hist_kernel<<<blocks, 256>>>(p_D, n4, shifts[p]);
            select_scan_kernel<<<1, 256>>>();
        }
        select_finalize_kernel<<<1, 1>>>(0);
    }
    // 4b) median of D2 (full 4-pass, tiny)
    {
        unsigned n = (unsigned)(DIM * DIM), n4 = n / 4;
        unsigned blocks = (n4 + 255u) / 256u;
        select_init_kernel<<<1, 256>>>((n - 1u) / 2u);
        const int shifts[4] = {24, 16, 8, 0};
        for (int p = 0; p < 4; p++) {
            select_hist_kernel<<<blocks, 256>>>(p_D2, n4, shifts[p]);
            select_scan_kernel<<<1, 256>>>();
        }
        select_finalize_kernel<<<1, 1>>>(1);
    }
    gamma_kernel<<<1, 1>>>();

    // 5) agent-expert similarity means from stored D
    rowsum_kernel<<<N, 256>>>(p_D);

    // 6) self-distance GEMM with fused rowsum (no D materialization)
    hmma_dist_gemm<1><<<ggrid, 256, GM_SMEM>>>(p_P, p_Q, p_x2, p_x2, nullptr);
    self_final_kernel<<<N / 256, 256>>>(out);
}

// round 8
// speedup vs baseline: 1.6073x; 1.1150x over previous
#include <cuda_runtime.h>
#include <cuda_bf16.h>
#include <cstdint>
#include <cmath>

// ---------------------------------------------------------------------------
// Shapes: n1 = n2 = 4096, s = 192, a = 64, d = 256. Split-GEMM K = 768.
// ---------------------------------------------------------------------------
#define N      4096
#define DIM    256
#define SDIM   192
#define ADIM   64
#define KSPLIT 768
#define EPS    1e-8f

// ---------------------------------------------------------------------------
// Scratch (device globals — allocations forbidden)
// ---------------------------------------------------------------------------
__device__ __align__(256) float g_sa [N * DIM];
__device__ __align__(256) float g_esa[N * DIM];
__device__ __align__(256) float g_x2 [N];
__device__ __align__(256) float g_y2 [N];
__device__ __align__(256) float g_D  [(size_t)N * N];        // 64 MB
__device__ __align__(256) float g_D2 [DIM * DIM];
__device__ __align__(256) float g_D2p[8 * DIM * DIM];
__device__ __align__(256) float g_c2part[128 * DIM];
__device__ __align__(256) float g_c2 [DIM];
__device__ __align__(256) float g_sim[N];
__device__ __align__(256) float g_selfpart [(size_t)N * 128]; // row-sum slots
__device__ __align__(256) float g_selfpart2[(size_t)N * 64];  // col-sum slots
__device__ __align__(256) __nv_bfloat16 g_P[(size_t)N * KSPLIT]; // sa  [hi|hi|lo]
__device__ __align__(256) __nv_bfloat16 g_Q[(size_t)N * KSPLIT]; // sa  [hi|lo|hi]
__device__ __align__(256) __nv_bfloat16 g_R[(size_t)N * KSPLIT]; // esa [hi|lo|hi]
__device__ unsigned g_hist[256];   // zero at start; scan re-zeroes after use
__device__ unsigned g_prefix;
__device__ unsigned g_k;
__device__ float    g_median[2];
__device__ float    g_gamma[2];

// ---------------------------------------------------------------------------
// helpers
// ---------------------------------------------------------------------------
__device__ __forceinline__ uint32_t smem_u32(const void* p) {
    uint32_t a;
    asm("{ .reg .u64 t; cvta.to.shared.u64 t, %1; cvt.u32.u64 %0, t; }"
        : "=r"(a) : "l"(p));
    return a;
}
#define SW128B(o) ((o) ^ (((o) >> 3) & 0x70))

__device__ __forceinline__ void cp_async16(uint32_t sdst, const void* gsrc) {
    asm volatile("cp.async.cg.shared.global [%0], [%1], 16;"
                 :: "r"(sdst), "l"(gsrc) : "memory");
}
__device__ __forceinline__ void cp_commit() {
    asm volatile("cp.async.commit_group;" ::: "memory");
}
__device__ __forceinline__ void ldmx4(uint32_t& r0, uint32_t& r1,
                                      uint32_t& r2, uint32_t& r3, uint32_t addr) {
    asm volatile("ldmatrix.sync.aligned.m8n8.x4.shared.b16 {%0,%1,%2,%3}, [%4];"
                 : "=r"(r0), "=r"(r1), "=r"(r2), "=r"(r3) : "r"(addr));
}
__device__ __forceinline__ void mma_bf16(float& c0, float& c1, float& c2, float& c3,
                                         uint32_t a0, uint32_t a1, uint32_t a2, uint32_t a3,
                                         uint32_t b0, uint32_t b1) {
    asm volatile(
        "mma.sync.aligned.m16n8k16.row.col.f32.bf16.bf16.f32 "
        "{%0,%1,%2,%3}, {%4,%5,%6,%7}, {%8,%9}, {%0,%1,%2,%3};"
        : "+f"(c0), "+f"(c1), "+f"(c2), "+f"(c3)
        : "r"(a0), "r"(a1), "r"(a2), "r"(a3), "r"(b0), "r"(b1));
}
__device__ __forceinline__ unsigned f2u_mono(float f) {
    unsigned b = __float_as_uint(f);
    return (b & 0x80000000u) ? ~b : (b | 0x80000000u);
}

// ---------------------------------------------------------------------------
// 1) concat + norm + bf16 hi/lo splits, fused.
// ---------------------------------------------------------------------------
__global__ void prep_kernel(const float* __restrict__ st,
                            const float* __restrict__ ac,
                            float* __restrict__ cat, float* __restrict__ nrm,
                            __nv_bfloat16* __restrict__ dst0, int phl0,
                            __nv_bfloat16* __restrict__ dst1) {
    int row = blockIdx.x, t = threadIdx.x;
    float v = (t < SDIM) ? st[row * SDIM + t] : ac[row * ADIM + (t - SDIM)];
    cat[row * DIM + t] = v;
    __nv_bfloat16 hi = __float2bfloat16(v);
    __nv_bfloat16 lo = __float2bfloat16(v - __bfloat162float(hi));
    size_t base = (size_t)row * KSPLIT + t;
    dst0[base]       = hi;
    dst0[base + 256] = phl0 ? hi : lo;
    dst0[base + 512] = phl0 ? lo : hi;
    if (dst1) { dst1[base] = hi; dst1[base + 256] = lo; dst1[base + 512] = hi; }

    __shared__ float sh[256];
    sh[t] = v * v;
    __syncthreads();
    #pragma unroll
    for (int s = 128; s > 0; s >>= 1) {
        if (t < s) sh[t] += sh[t + s];
        __syncthreads();
    }
    if (t == 0) nrm[row] = sh[0];
}

// ---------------------------------------------------------------------------
// 2) HMMA distance GEMM — proven geometry: 128x128 CTA tile, 8 warps (2x4)
//    of 64x32, BK=64, 2-stage cp.async, SW128 smem, K = 768.
//    MODE 0: full grid; store D + fused MSB histogram.
//    MODE 1: triangular grid (528 tiles); fused self row+col exp-sums, no D.
// ---------------------------------------------------------------------------
#define BK        64
#define TILE_B    (128 * BK * 2)          // 16 KB per operand per stage
#define GM_SMEM   (4 * TILE_B)            // 64 KB
#define NCHUNK    12
#define NTILE     32                      // 4096/128
#define NTRI      (NTILE * (NTILE + 1) / 2)  // 528

__device__ __forceinline__ void gemm_issue_stage(
    const __nv_bfloat16* __restrict__ A, const __nv_bfloat16* __restrict__ B,
    int i0, int j0, int c, uint32_t sA, uint32_t sB, int tid)
{
    const __nv_bfloat16* Ap = A + (size_t)i0 * KSPLIT + c * BK;
    const __nv_bfloat16* Bp = B + (size_t)j0 * KSPLIT + c * BK;
    #pragma unroll
    for (int q = 0; q < 4; q++) {
        int idx = tid + q * 256;
        int row = idx >> 3, seg = idx & 7;
        cp_async16(sA + SW128B(row * 128 + seg * 16),
                   Ap + (size_t)row * KSPLIT + seg * 8);
    }
    #pragma unroll
    for (int q = 0; q < 4; q++) {
        int idx = tid + q * 256;
        int row = idx >> 3, seg = idx & 7;
        cp_async16(sB + SW128B(row * 128 + seg * 16),
                   Bp + (size_t)row * KSPLIT + seg * 8);
    }
    cp_commit();
}

template <int MODE>
__global__ __launch_bounds__(256, 1)
void hmma_dist_gemm(const __nv_bfloat16* __restrict__ A,
                    const __nv_bfloat16* __restrict__ B,
                    const float* __restrict__ x2,
                    const float* __restrict__ y2,
                    float* __restrict__ D)
{
    extern __shared__ char smem[];
    const uint32_t sb = smem_u32(smem);
    const int tid = threadIdx.x;
    const int wid = tid >> 5, lane = tid & 31;
    const int warp_m = wid >> 2, warp_n = wid & 3;   // 2 x 4 warps

    int ti, tj;
    if (MODE == 1) {
        // decode upper-triangular tile index (tj >= ti)
        int bid = blockIdx.x;
        ti = (int)(32.5f - sqrtf(32.5f * 32.5f - 2.0f * (float)bid));
        while (NTILE * ti - ti * (ti - 1) / 2 > bid) ti--;
        while (NTILE * (ti + 1) - (ti + 1) * ti / 2 <= bid) ti++;
        tj = ti + (bid - (NTILE * ti - ti * (ti - 1) / 2));
    } else {
        ti = blockIdx.y;
        tj = blockIdx.x;
    }
    const int i0 = ti * 128;
    const int j0 = tj * 128;

    uint32_t sA[2] = { sb,          sb + 2 * TILE_B };
    uint32_t sB[2] = { sb + TILE_B, sb + 3 * TILE_B };

    float acc[4][4][4];
    #pragma unroll
    for (int mi = 0; mi < 4; mi++)
        #pragma unroll
        for (int ni = 0; ni < 4; ni++)
            #pragma unroll
            for (int e = 0; e < 4; e++) acc[mi][ni][e] = 0.f;

    gemm_issue_stage(A, B, i0, j0, 0, sA[0], sB[0], tid);
    gemm_issue_stage(A, B, i0, j0, 1, sA[1], sB[1], tid);

    const int a_row = (lane & 15);
    const int a_col = (lane & 16) ? 8 : 0;
    const int b_row = (lane & 7) + ((lane & 16) >> 1);
    const int b_col = (lane & 8) ? 8 : 0;

    for (int c = 0; c < NCHUNK; c++) {
        if (c < NCHUNK - 2) asm volatile("cp.async.wait_group 1;" ::: "memory");
        else                asm volatile("cp.async.wait_group 0;" ::: "memory");
        __syncthreads();

        uint32_t cA = sA[c & 1], cB = sB[c & 1];
        #pragma unroll
        for (int ks = 0; ks < BK / 16; ks++) {
            int k0 = ks * 16;
            uint32_t a[4][4], b[2][4];
            #pragma unroll
            for (int mi = 0; mi < 4; mi++) {
                int row = warp_m * 64 + mi * 16 + a_row;
                ldmx4(a[mi][0], a[mi][1], a[mi][2], a[mi][3],
                      cA + SW128B(row * 128 + (k0 + a_col) * 2));
            }
            #pragma unroll
            for (int nb = 0; nb < 2; nb++) {
                int row = warp_n * 32 + nb * 16 + b_row;
                ldmx4(b[nb][0], b[nb][1], b[nb][2], b[nb][3],
                      cB + SW128B(row * 128 + (k0 + b_col) * 2));
            }
            #pragma unroll
            for (int mi = 0; mi < 4; mi++)
                #pragma unroll
                for (int ni = 0; ni < 4; ni++)
                    mma_bf16(acc[mi][ni][0], acc[mi][ni][1],
                             acc[mi][ni][2], acc[mi][ni][3],
                             a[mi][0], a[mi][1], a[mi][2], a[mi][3],
                             b[ni >> 1][(ni & 1) * 2], b[ni >> 1][(ni & 1) * 2 + 1]);
        }
        __syncthreads();
        if (c + 2 < NCHUNK)
            gemm_issue_stage(A, B, i0, j0, c + 2, sA[c & 1], sB[c & 1], tid);
    }

    const int qrow = lane >> 2;            // 0..7
    const int qcol = (lane & 3) * 2;       // 0,2,4,6

    if (MODE == 0) {
        // -------- store D + run-length aggregated MSB histogram --------
        unsigned* hsh = (unsigned*)smem;
        hsh[tid] = 0u;
        __syncthreads();
        unsigned lastb = 0xFFFFFFFFu, cnt = 0;

        #pragma unroll
        for (int mi = 0; mi < 4; mi++) {
            int i_lo = i0 + warp_m * 64 + mi * 16 + qrow;
            int i_hi = i_lo + 8;
            float xlo = x2[i_lo], xhi = x2[i_hi];
            #pragma unroll
            for (int ni = 0; ni < 4; ni++) {
                int j = j0 + warp_n * 32 + ni * 8 + qcol;
                float yj0 = y2[j], yj1 = y2[j + 1];
                float2 vlo, vhi;
                vlo.x = (xlo + yj0 - 2.f * acc[mi][ni][0]) * 0.00390625f;
                vlo.y = (xlo + yj1 - 2.f * acc[mi][ni][1]) * 0.00390625f;
                vhi.x = (xhi + yj0 - 2.f * acc[mi][ni][2]) * 0.00390625f;
                vhi.y = (xhi + yj1 - 2.f * acc[mi][ni][3]) * 0.00390625f;
                *(float2*)(D + (size_t)i_lo * N + j) = vlo;
                *(float2*)(D + (size_t)i_hi * N + j) = vhi;
                float vs[4] = {vlo.x, vlo.y, vhi.x, vhi.y};
                #pragma unroll
                for (int e = 0; e < 4; e++) {
                    unsigned bk = f2u_mono(vs[e]) >> 24;
                    if (bk == lastb) cnt++;
                    else {
                        if (cnt) atomicAdd(&hsh[lastb], cnt);
                        lastb = bk; cnt = 1;
                    }
                }
            }
        }
        if (cnt) atomicAdd(&hsh[lastb], cnt);
        __syncthreads();
        if (hsh[tid]) atomicAdd(&g_hist[tid], hsh[tid]);
    } else {
        // -------- fused self row+col exp-sums (triangular; no D store) ------
        float g1 = g_gamma[0], g2 = g_gamma[1];
        float csum[4][2];
        #pragma unroll
        for (int ni = 0; ni < 4; ni++) { csum[ni][0] = 0.f; csum[ni][1] = 0.f; }

        #pragma unroll
        for (int mi = 0; mi < 4; mi++) {
            int i_lo = i0 + warp_m * 64 + mi * 16 + qrow;
            int i_hi = i_lo + 8;
            float xlo = x2[i_lo], xhi = x2[i_hi];
            float slo = 0.f, shi = 0.f;
            #pragma unroll
            for (int ni = 0; ni < 4; ni++) {
                int j = j0 + warp_n * 32 + ni * 8 + qcol;
                float yj0 = y2[j], yj1 = y2[j + 1];
                float d0 = (xlo + yj0 - 2.f * acc[mi][ni][0]) * 0.00390625f;
                float d1 = (xlo + yj1 - 2.f * acc[mi][ni][1]) * 0.00390625f;
                float d2v = (xhi + yj0 - 2.f * acc[mi][ni][2]) * 0.00390625f;
                float d3 = (xhi + yj1 - 2.f * acc[mi][ni][3]) * 0.00390625f;
                float e0 = __expf(-g1 * d0)  + __expf(-g2 * d0);
                float e1 = __expf(-g1 * d1)  + __expf(-g2 * d1);
                float e2 = __expf(-g1 * d2v) + __expf(-g2 * d2v);
                float e3 = __expf(-g1 * d3)  + __expf(-g2 * d3);
                slo += e0 + e1;
                shi += e2 + e3;
                csum[ni][0] += e0 + e2;
                csum[ni][1] += e1 + e3;
            }
            slo += __shfl_xor_sync(0xFFFFFFFFu, slo, 1);
            slo += __shfl_xor_sync(0xFFFFFFFFu, slo, 2);
            shi += __shfl_xor_sync(0xFFFFFFFFu, shi, 1);
            shi += __shfl_xor_sync(0xFFFFFFFFu, shi, 2);
            if ((lane & 3) == 0) {
                int col = tj * 4 + warp_n;               // 0..127
                g_selfpart[(size_t)i_lo * 128 + col] = slo;
                g_selfpart[(size_t)i_hi * 128 + col] = shi;
            }
        }
        if (ti != tj) {
            // column sums -> mirrored rows (j as row index)
            #pragma unroll
            for (int ni = 0; ni < 4; ni++) {
                #pragma unroll
                for (int cc = 0; cc < 2; cc++) {
                    float v = csum[ni][cc];
                    v += __shfl_xor_sync(0xFFFFFFFFu, v, 4);
                    v += __shfl_xor_sync(0xFFFFFFFFu, v, 8);
                    v += __shfl_xor_sync(0xFFFFFFFFu, v, 16);
                    if (lane < 4) {
                        int j = j0 + warp_n * 32 + ni * 8 + lane * 2 + cc;
                        g_selfpart2[(size_t)j * 64 + ti * 2 + warp_m] = v;
                    }
                }
            }
        }
    }
}

// ---------------------------------------------------------------------------
// 3) gamma_2 path
// ---------------------------------------------------------------------------
__global__ void colnorm_part_kernel() {
    int b = blockIdx.x, t = threadIdx.x;   // 128 blocks, 32 rows each
    float s = 0.f;
    int r0 = b * 32;
    for (int r = 0; r < 32; r++) {
        float v = g_esa[(size_t)(r0 + r) * DIM + t];
        s += v * v;
    }
    g_c2part[b * DIM + t] = s;
}
__global__ void colnorm_reduce_kernel() {
    int t = threadIdx.x;
    float s = 0.f;
    for (int b = 0; b < 128; b++) s += g_c2part[b * DIM + t];
    g_c2[t] = s;
}
__global__ __launch_bounds__(256)
void d2_part_kernel() {
    __shared__ float Ei[64][32];
    __shared__ float Ej[64][32];
    const int tx = threadIdx.x & 15, ty = threadIdx.x >> 4;
    const int i0 = blockIdx.y * 32, j0 = blockIdx.x * 32;
    const int k0 = blockIdx.z * 512;
    float a00 = 0, a01 = 0, a10 = 0, a11 = 0;
    for (int kc = k0; kc < k0 + 512; kc += 64) {
        #pragma unroll
        for (int r = 0; r < 8; r++) {
            int idx = threadIdx.x + r * 256;
            int kk = idx >> 5, col = idx & 31;
            Ei[kk][col] = g_esa[(size_t)(kc + kk) * DIM + i0 + col];
            Ej[kk][col] = g_esa[(size_t)(kc + kk) * DIM + j0 + col];
        }
        __syncthreads();
        #pragma unroll
        for (int kk = 0; kk < 64; kk++) {
            float xa = Ei[kk][ty], xb = Ei[kk][ty + 16];
            float ya = Ej[kk][tx], yb = Ej[kk][tx + 16];
            a00 += xa * ya; a01 += xa * yb; a10 += xb * ya; a11 += xb * yb;
        }
        __syncthreads();
    }
    float* P = g_D2p + (size_t)blockIdx.z * DIM * DIM;
    P[(i0 + ty) * DIM + j0 + tx]           = a00;
    P[(i0 + ty) * DIM + j0 + tx + 16]      = a01;
    P[(i0 + ty + 16) * DIM + j0 + tx]      = a10;
    P[(i0 + ty + 16) * DIM + j0 + tx + 16] = a11;
}
__global__ void d2_final_kernel() {
    int i = blockIdx.x, j = threadIdx.x;
    float s = 0.f;
    #pragma unroll
    for (int z = 0; z < 8; z++) s += g_D2p[(size_t)z * DIM * DIM + i * DIM + j];
    g_D2[i * DIM + j] = (g_c2[i] + g_c2[j] - 2.f * s) * (1.f / 4096.f);
}

// ---------------------------------------------------------------------------
// 4) radix select
// ---------------------------------------------------------------------------
__global__ void select_init_kernel(unsigned k) {
    if (threadIdx.x == 0) { g_prefix = 0u; g_k = k; }
    g_hist[threadIdx.x] = 0u;
}
__global__ void select_setpk_kernel(unsigned k) {
    g_prefix = 0u; g_k = k;
}
__global__ void select_hist_kernel(const float* __restrict__ data, unsigned n4, int shift) {
    __shared__ unsigned sh[256];
    sh[threadIdx.x] = 0u;
    __syncthreads();
    unsigned prefix = g_prefix;
    unsigned stride = gridDim.x * blockDim.x;
    int lane = threadIdx.x & 31;
    const float4* d4 = (const float4*)data;
    for (unsigned base = blockIdx.x * blockDim.x; base < n4; base += stride) {
        unsigned i = base + threadIdx.x;
        float4 v = make_float4(0.f, 0.f, 0.f, 0.f);
        bool valid = (i < n4);
        if (valid) v = d4[i];
        float vals[4] = {v.x, v.y, v.z, v.w};
        #pragma unroll
        for (int e = 0; e < 4; e++) {
            unsigned bucket = 0xFFFFFFFFu;
            if (valid) {
                unsigned u = f2u_mono(vals[e]);
                bool ok = (shift == 24) || ((u >> (shift + 8)) == prefix);
                if (ok) bucket = (u >> shift) & 0xFFu;
            }
            unsigned m = __match_any_sync(0xFFFFFFFFu, bucket);
            if (bucket != 0xFFFFFFFFu && lane == __ffs(m) - 1)
                atomicAdd(&sh[bucket], (unsigned)__popc(m));
        }
    }
    __syncthreads();
    if (sh[threadIdx.x]) atomicAdd(&g_hist[threadIdx.x], sh[threadIdx.x]);
}
__global__ void select_scan_kernel() {
    __shared__ unsigned s[256];
    int t = threadIdx.x;
    unsigned c = g_hist[t];
    s[t] = c;
    __syncthreads();
    for (int off = 1; off < 256; off <<= 1) {
        unsigned v = (t >= off) ? s[t - off] : 0u;
        __syncthreads();
        s[t] += v;
        __syncthreads();
    }
    unsigned k = g_k;
    unsigned incl = s[t], excl = incl - c;
    if (k >= excl && k < incl) {
        g_k = k - excl;
        g_prefix = (g_prefix << 8) | (unsigned)t;
    }
    g_hist[t] = 0u;
}
__global__ void select_finalize_kernel(int idx) {
    unsigned u = g_prefix;
    unsigned bits = (u & 0x80000000u) ? (u ^ 0x80000000u) : ~u;
    g_median[idx] = __uint_as_float(bits);
}
__global__ void gamma_kernel() {
    g_gamma[0] = 1.0f / (g_median[0] + EPS);
    g_gamma[1] = 1.0f / (g_median[1] + EPS);
}

// ---------------------------------------------------------------------------
// 5) Row means of exp over stored D (agent-expert pass)
// ---------------------------------------------------------------------------
__global__ __launch_bounds__(256)
void rowsum_kernel(const float* __restrict__ D) {
    int i = blockIdx.x, t = threadIdx.x;
    float g1 = g_gamma[0], g2 = g_gamma[1];
    const float4* row = (const float4*)(D + (size_t)i * N);
    float s = 0.f;
    #pragma unroll 4
    for (int j = t; j < N / 4; j += 256) {
        float4 v = row[j];
        s += __expf(-g1 * v.x) + __expf(-g1 * v.y) + __expf(-g1 * v.z) + __expf(-g1 * v.w)
           + __expf(-g2 * v.x) + __expf(-g2 * v.y) + __expf(-g2 * v.z) + __expf(-g2 * v.w);
    }
    __shared__ float sh[256];
    sh[t] = s;
    __syncthreads();
    #pragma unroll
    for (int k = 128; k > 0; k >>= 1) {
        if (t < k) sh[t] += sh[t + k];
        __syncthreads();
    }
    if (t == 0) g_sim[i] = sh[0] * (1.0f / (float)N);
}

// ---------------------------------------------------------------------------
// 6) final: out[i] = g_sim[i] - mean of valid self partials
//    row-slots valid: [4t, 128);  col-slots valid: [0, 2t)   (t = i/128)
// ---------------------------------------------------------------------------
__global__ void self_final_kernel(float* __restrict__ out) {
    int i = blockIdx.x * blockDim.x + threadIdx.x;
    int t = i >> 7;
    const float* rp = g_selfpart  + (size_t)i * 128;
    const float* cp = g_selfpart2 + (size_t)i * 64;
    float s = 0.f;
    for (int b = 4 * t; b < 128; b++) s += rp[b];
    for (int b = 0; b < 2 * t; b++)  s += cp[b];
    out[i] = g_sim[i] - s * (1.0f / (float)N);
}

// ---------------------------------------------------------------------------
// Host orchestration (graph-capturable)
// ---------------------------------------------------------------------------
extern "C" void kernel_launch(void* const* d_in, const int* in_sizes, int n_in,
                              void* d_out, int out_size) {
    const float* state   = (const float*)d_in[0];
    const float* action  = (const float*)d_in[1];
    const float* estate  = (const float*)d_in[2];
    const float* eaction = (const float*)d_in[3];
    float* out = (float*)d_out;

    float *p_sa, *p_esa, *p_x2, *p_y2, *p_D, *p_D2;
    __nv_bfloat16 *p_P, *p_Q, *p_R;
    cudaGetSymbolAddress((void**)&p_sa,  g_sa);
    cudaGetSymbolAddress((void**)&p_esa, g_esa);
    cudaGetSymbolAddress((void**)&p_x2,  g_x2);
    cudaGetSymbolAddress((void**)&p_y2,  g_y2);
    cudaGetSymbolAddress((void**)&p_D,   g_D);
    cudaGetSymbolAddress((void**)&p_D2,  g_D2);
    cudaGetSymbolAddress((void**)&p_P,   g_P);
    cudaGetSymbolAddress((void**)&p_Q,   g_Q);
    cudaGetSymbolAddress((void**)&p_R,   g_R);

    cudaFuncSetAttribute(hmma_dist_gemm<0>,
                         cudaFuncAttributeMaxDynamicSharedMemorySize, GM_SMEM);
    cudaFuncSetAttribute(hmma_dist_gemm<1>,
                         cudaFuncAttributeMaxDynamicSharedMemorySize, GM_SMEM);

    // 1) concat + norms + bf16 splits (fused; expert MUST be [hi|lo|hi])
    prep_kernel<<<N, 256>>>(state,  action,  p_sa,  p_x2, p_P, 1, p_Q);
    prep_kernel<<<N, 256>>>(estate, eaction, p_esa, p_y2, p_R, 0, nullptr);

    // 2) D_agent_expert + fused MSB histogram
    dim3 ggrid(N / 128, N / 128);
    hmma_dist_gemm<0><<<ggrid, 256, GM_SMEM>>>(p_P, p_R, p_x2, p_y2, p_D);

    // 3) gamma_2 small distance matrix
    colnorm_part_kernel<<<128, 256>>>();
    colnorm_reduce_kernel<<<1, 256>>>();
    d2_part_kernel<<<dim3(8, 8, 8), 256>>>();
    d2_final_kernel<<<DIM, DIM>>>();

    // 4a) median of D: pass 1 from the fused histogram
    {
        unsigned n = (unsigned)N * (unsigned)N;
        unsigned n4 = n / 4;
        unsigned blocks = (n4 + 255u) / 256u;
        if (blocks > 2048u) blocks = 2048u;
        select_setpk_kernel<<<1, 1>>>((n - 1u) / 2u);
        select_scan_kernel<<<1, 256>>>();                 // consume fused hist
        const int shifts[3] = {16, 8, 0};
        for (int p = 0; p < 3; p++) {
            select_hist_kernel<<<blocks, 256>>>(p_D, n4, shifts[p]);
            select_scan_kernel<<<1, 256>>>();
        }
        select_finalize_kernel<<<1, 1>>>(0);
    }
    // 4b) median of D2 (full 4-pass, tiny)
    {
        unsigned n = (unsigned)(DIM * DIM), n4 = n / 4;
        unsigned blocks = (n4 + 255u) / 256u;
        select_init_kernel<<<1, 256>>>((n - 1u) / 2u);
        const int shifts[4] = {24, 16, 8, 0};
        for (int p = 0; p < 4; p++) {
            select_hist_kernel<<<blocks, 256>>>(p_D2, n4, shifts[p]);
            select_scan_kernel<<<1, 256>>>();
        }
        select_finalize_kernel<<<1, 1>>>(1);
    }
    gamma_kernel<<<1, 1>>>();

    // 5) agent-expert similarity means from stored D
    rowsum_kernel<<<N, 256>>>(p_D);

    // 6) self-distance GEMM, upper-triangular tiles only, fused row+col sums
    hmma_dist_gemm<1><<<NTRI, 256, GM_SMEM>>>(p_P, p_Q, p_x2, p_x2, nullptr);
    self_final_kernel<<<N / 256, 256>>>(out);
}

// round 9
// speedup vs baseline: 1.7655x; 1.0984x over previous
#include <cuda_runtime.h>
#include <cuda_bf16.h>
#include <cstdint>
#include <cmath>

// ---------------------------------------------------------------------------
// Shapes: n1 = n2 = 4096, s = 192, a = 64, d = 256. Split-GEMM K = 768.
// ---------------------------------------------------------------------------
#define N      4096
#define DIM    256
#define SDIM   192
#define ADIM   64
#define KSPLIT 768
#define EPS    1e-8f

// ---------------------------------------------------------------------------
// Scratch (device globals — allocations forbidden)
// ---------------------------------------------------------------------------
__device__ __align__(256) float g_sa [N * DIM];
__device__ __align__(256) float g_esa[N * DIM];
__device__ __align__(256) float g_x2 [N];
__device__ __align__(256) float g_y2 [N];
__device__ __align__(256) float g_D  [(size_t)N * N];        // 64 MB
__device__ __align__(256) float g_D2 [DIM * DIM];
__device__ __align__(256) float g_D2p[8 * DIM * DIM];
__device__ __align__(256) float g_c2part[128 * DIM];
__device__ __align__(256) float g_c2 [DIM];
__device__ __align__(256) float g_sim[N];
__device__ __align__(256) float g_selfpart [(size_t)N * 128]; // row-sum slots
__device__ __align__(256) float g_selfpart2[(size_t)N * 64];  // col-sum slots
__device__ __align__(256) __nv_bfloat16 g_P[(size_t)N * KSPLIT]; // sa  [hi|hi|lo]
__device__ __align__(256) __nv_bfloat16 g_Q[(size_t)N * KSPLIT]; // sa  [hi|lo|hi]
__device__ __align__(256) __nv_bfloat16 g_R[(size_t)N * KSPLIT]; // esa [hi|lo|hi]
__device__ unsigned g_hist4[4 * 256];  // per-pass histograms (prep zeroes)
__device__ float    g_median[2];
__device__ float    g_gamma[2];

#define K_TARGET 8388607u   // (N*N - 1) / 2

// ---------------------------------------------------------------------------
// helpers
// ---------------------------------------------------------------------------
__device__ __forceinline__ uint32_t smem_u32(const void* p) {
    uint32_t a;
    asm("{ .reg .u64 t; cvta.to.shared.u64 t, %1; cvt.u32.u64 %0, t; }"
        : "=r"(a) : "l"(p));
    return a;
}
#define SW128B(o) ((o) ^ (((o) >> 3) & 0x70))

__device__ __forceinline__ void cp_async16(uint32_t sdst, const void* gsrc) {
    asm volatile("cp.async.cg.shared.global [%0], [%1], 16;"
                 :: "r"(sdst), "l"(gsrc) : "memory");
}
__device__ __forceinline__ void cp_commit() {
    asm volatile("cp.async.commit_group;" ::: "memory");
}
__device__ __forceinline__ void ldmx4(uint32_t& r0, uint32_t& r1,
                                      uint32_t& r2, uint32_t& r3, uint32_t addr) {
    asm volatile("ldmatrix.sync.aligned.m8n8.x4.shared.b16 {%0,%1,%2,%3}, [%4];"
                 : "=r"(r0), "=r"(r1), "=r"(r2), "=r"(r3) : "r"(addr));
}
__device__ __forceinline__ void mma_bf16(float& c0, float& c1, float& c2, float& c3,
                                         uint32_t a0, uint32_t a1, uint32_t a2, uint32_t a3,
                                         uint32_t b0, uint32_t b1) {
    asm volatile(
        "mma.sync.aligned.m16n8k16.row.col.f32.bf16.bf16.f32 "
        "{%0,%1,%2,%3}, {%4,%5,%6,%7}, {%8,%9}, {%0,%1,%2,%3};"
        : "+f"(c0), "+f"(c1), "+f"(c2), "+f"(c3)
        : "r"(a0), "r"(a1), "r"(a2), "r"(a3), "r"(b0), "r"(b1));
}
__device__ __forceinline__ unsigned f2u_mono(float f) {
    unsigned b = __float_as_uint(f);
    return (b & 0x80000000u) ? ~b : (b | 0x80000000u);
}

// ---------------------------------------------------------------------------
// 1) concat + norm + bf16 hi/lo splits, fused. Also zeroes g_hist4.
// ---------------------------------------------------------------------------
__global__ void prep_kernel(const float* __restrict__ st,
                            const float* __restrict__ ac,
                            float* __restrict__ cat, float* __restrict__ nrm,
                            __nv_bfloat16* __restrict__ dst0, int phl0,
                            __nv_bfloat16* __restrict__ dst1) {
    int row = blockIdx.x, t = threadIdx.x;
    if (blockIdx.x < 4) g_hist4[blockIdx.x * 256 + t] = 0u;
    float v = (t < SDIM) ? st[row * SDIM + t] : ac[row * ADIM + (t - SDIM)];
    cat[row * DIM + t] = v;
    __nv_bfloat16 hi = __float2bfloat16(v);
    __nv_bfloat16 lo = __float2bfloat16(v - __bfloat162float(hi));
    size_t base = (size_t)row * KSPLIT + t;
    dst0[base]       = hi;
    dst0[base + 256] = phl0 ? hi : lo;
    dst0[base + 512] = phl0 ? lo : hi;
    if (dst1) { dst1[base] = hi; dst1[base + 256] = lo; dst1[base + 512] = hi; }

    __shared__ float sh[256];
    sh[t] = v * v;
    __syncthreads();
    #pragma unroll
    for (int s = 128; s > 0; s >>= 1) {
        if (t < s) sh[t] += sh[t + s];
        __syncthreads();
    }
    if (t == 0) nrm[row] = sh[0];
}

// ---------------------------------------------------------------------------
// 2) HMMA distance GEMM — 128x128 CTA tile, 8 warps (2x4) of 64x32, BK=64,
//    2-stage cp.async, SW128 smem, K = 768, forced 2 CTAs/SM.
//    MODE 0: full grid; store D + fused MSB histogram -> g_hist4[0].
//    MODE 1: triangular grid (528 tiles); fused self row+col exp-sums, no D.
// ---------------------------------------------------------------------------
#define BK        64
#define TILE_B    (128 * BK * 2)
#define GM_SMEM   (4 * TILE_B)            // 64 KB
#define NCHUNK    12
#define NTILE     32
#define NTRI      (NTILE * (NTILE + 1) / 2)

__device__ __forceinline__ void gemm_issue_stage(
    const __nv_bfloat16* __restrict__ A, const __nv_bfloat16* __restrict__ B,
    int i0, int j0, int c, uint32_t sA, uint32_t sB, int tid)
{
    const __nv_bfloat16* Ap = A + (size_t)i0 * KSPLIT + c * BK;
    const __nv_bfloat16* Bp = B + (size_t)j0 * KSPLIT + c * BK;
    #pragma unroll
    for (int q = 0; q < 4; q++) {
        int idx = tid + q * 256;
        int row = idx >> 3, seg = idx & 7;
        cp_async16(sA + SW128B(row * 128 + seg * 16),
                   Ap + (size_t)row * KSPLIT + seg * 8);
    }
    #pragma unroll
    for (int q = 0; q < 4; q++) {
        int idx = tid + q * 256;
        int row = idx >> 3, seg = idx & 7;
        cp_async16(sB + SW128B(row * 128 + seg * 16),
                   Bp + (size_t)row * KSPLIT + seg * 8);
    }
    cp_commit();
}

template <int MODE>
__global__ __launch_bounds__(256, 2)
void hmma_dist_gemm(const __nv_bfloat16* __restrict__ A,
                    const __nv_bfloat16* __restrict__ B,
                    const float* __restrict__ x2,
                    const float* __restrict__ y2,
                    float* __restrict__ D)
{
    extern __shared__ char smem[];
    const uint32_t sb = smem_u32(smem);
    const int tid = threadIdx.x;
    const int wid = tid >> 5, lane = tid & 31;
    const int warp_m = wid >> 2, warp_n = wid & 3;   // 2 x 4 warps

    int ti, tj;
    if (MODE == 1) {
        int bid = blockIdx.x;
        ti = (int)(32.5f - sqrtf(32.5f * 32.5f - 2.0f * (float)bid));
        while (NTILE * ti - ti * (ti - 1) / 2 > bid) ti--;
        while (NTILE * (ti + 1) - (ti + 1) * ti / 2 <= bid) ti++;
        tj = ti + (bid - (NTILE * ti - ti * (ti - 1) / 2));
    } else {
        ti = blockIdx.y;
        tj = blockIdx.x;
    }
    const int i0 = ti * 128;
    const int j0 = tj * 128;

    uint32_t sA[2] = { sb,          sb + 2 * TILE_B };
    uint32_t sB[2] = { sb + TILE_B, sb + 3 * TILE_B };

    float acc[4][4][4];
    #pragma unroll
    for (int mi = 0; mi < 4; mi++)
        #pragma unroll
        for (int ni = 0; ni < 4; ni++)
            #pragma unroll
            for (int e = 0; e < 4; e++) acc[mi][ni][e] = 0.f;

    gemm_issue_stage(A, B, i0, j0, 0, sA[0], sB[0], tid);
    gemm_issue_stage(A, B, i0, j0, 1, sA[1], sB[1], tid);

    const int a_row = (lane & 15);
    const int a_col = (lane & 16) ? 8 : 0;
    const int b_row = (lane & 7) + ((lane & 16) >> 1);
    const int b_col = (lane & 8) ? 8 : 0;

    for (int c = 0; c < NCHUNK; c++) {
        if (c < NCHUNK - 2) asm volatile("cp.async.wait_group 1;" ::: "memory");
        else                asm volatile("cp.async.wait_group 0;" ::: "memory");
        __syncthreads();

        uint32_t cA = sA[c & 1], cB = sB[c & 1];
        #pragma unroll
        for (int ks = 0; ks < BK / 16; ks++) {
            int k0 = ks * 16;
            uint32_t a[4][4], b[2][4];
            #pragma unroll
            for (int mi = 0; mi < 4; mi++) {
                int row = warp_m * 64 + mi * 16 + a_row;
                ldmx4(a[mi][0], a[mi][1], a[mi][2], a[mi][3],
                      cA + SW128B(row * 128 + (k0 + a_col) * 2));
            }
            #pragma unroll
            for (int nb = 0; nb < 2; nb++) {
                int row = warp_n * 32 + nb * 16 + b_row;
                ldmx4(b[nb][0], b[nb][1], b[nb][2], b[nb][3],
                      cB + SW128B(row * 128 + (k0 + b_col) * 2));
            }
            #pragma unroll
            for (int mi = 0; mi < 4; mi++)
                #pragma unroll
                for (int ni = 0; ni < 4; ni++)
                    mma_bf16(acc[mi][ni][0], acc[mi][ni][1],
                             acc[mi][ni][2], acc[mi][ni][3],
                             a[mi][0], a[mi][1], a[mi][2], a[mi][3],
                             b[ni >> 1][(ni & 1) * 2], b[ni >> 1][(ni & 1) * 2 + 1]);
        }
        __syncthreads();
        if (c + 2 < NCHUNK)
            gemm_issue_stage(A, B, i0, j0, c + 2, sA[c & 1], sB[c & 1], tid);
    }

    const int qrow = lane >> 2;
    const int qcol = (lane & 3) * 2;

    if (MODE == 0) {
        unsigned* hsh = (unsigned*)smem;
        hsh[tid] = 0u;
        __syncthreads();
        unsigned lastb = 0xFFFFFFFFu, cnt = 0;

        #pragma unroll
        for (int mi = 0; mi < 4; mi++) {
            int i_lo = i0 + warp_m * 64 + mi * 16 + qrow;
            int i_hi = i_lo + 8;
            float xlo = x2[i_lo], xhi = x2[i_hi];
            #pragma unroll
            for (int ni = 0; ni < 4; ni++) {
                int j = j0 + warp_n * 32 + ni * 8 + qcol;
                float yj0 = y2[j], yj1 = y2[j + 1];
                float2 vlo, vhi;
                vlo.x = (xlo + yj0 - 2.f * acc[mi][ni][0]) * 0.00390625f;
                vlo.y = (xlo + yj1 - 2.f * acc[mi][ni][1]) * 0.00390625f;
                vhi.x = (xhi + yj0 - 2.f * acc[mi][ni][2]) * 0.00390625f;
                vhi.y = (xhi + yj1 - 2.f * acc[mi][ni][3]) * 0.00390625f;
                *(float2*)(D + (size_t)i_lo * N + j) = vlo;
                *(float2*)(D + (size_t)i_hi * N + j) = vhi;
                float vs[4] = {vlo.x, vlo.y, vhi.x, vhi.y};
                #pragma unroll
                for (int e = 0; e < 4; e++) {
                    unsigned bk = f2u_mono(vs[e]) >> 24;
                    if (bk == lastb) cnt++;
                    else {
                        if (cnt) atomicAdd(&hsh[lastb], cnt);
                        lastb = bk; cnt = 1;
                    }
                }
            }
        }
        if (cnt) atomicAdd(&hsh[lastb], cnt);
        __syncthreads();
        if (hsh[tid]) atomicAdd(&g_hist4[tid], hsh[tid]);
    } else {
        float g1 = g_gamma[0], g2 = g_gamma[1];
        float csum[4][2];
        #pragma unroll
        for (int ni = 0; ni < 4; ni++) { csum[ni][0] = 0.f; csum[ni][1] = 0.f; }

        #pragma unroll
        for (int mi = 0; mi < 4; mi++) {
            int i_lo = i0 + warp_m * 64 + mi * 16 + qrow;
            int i_hi = i_lo + 8;
            float xlo = x2[i_lo], xhi = x2[i_hi];
            float slo = 0.f, shi = 0.f;
            #pragma unroll
            for (int ni = 0; ni < 4; ni++) {
                int j = j0 + warp_n * 32 + ni * 8 + qcol;
                float yj0 = y2[j], yj1 = y2[j + 1];
                float d0 = (xlo + yj0 - 2.f * acc[mi][ni][0]) * 0.00390625f;
                float d1 = (xlo + yj1 - 2.f * acc[mi][ni][1]) * 0.00390625f;
                float d2v = (xhi + yj0 - 2.f * acc[mi][ni][2]) * 0.00390625f;
                float d3 = (xhi + yj1 - 2.f * acc[mi][ni][3]) * 0.00390625f;
                float e0 = __expf(-g1 * d0)  + __expf(-g2 * d0);
                float e1 = __expf(-g1 * d1)  + __expf(-g2 * d1);
                float e2 = __expf(-g1 * d2v) + __expf(-g2 * d2v);
                float e3 = __expf(-g1 * d3)  + __expf(-g2 * d3);
                slo += e0 + e1;
                shi += e2 + e3;
                csum[ni][0] += e0 + e2;
                csum[ni][1] += e1 + e3;
            }
            slo += __shfl_xor_sync(0xFFFFFFFFu, slo, 1);
            slo += __shfl_xor_sync(0xFFFFFFFFu, slo, 2);
            shi += __shfl_xor_sync(0xFFFFFFFFu, shi, 1);
            shi += __shfl_xor_sync(0xFFFFFFFFu, shi, 2);
            if ((lane & 3) == 0) {
                int col = tj * 4 + warp_n;
                g_selfpart[(size_t)i_lo * 128 + col] = slo;
                g_selfpart[(size_t)i_hi * 128 + col] = shi;
            }
        }
        if (ti != tj) {
            #pragma unroll
            for (int ni = 0; ni < 4; ni++) {
                #pragma unroll
                for (int cc = 0; cc < 2; cc++) {
                    float v = csum[ni][cc];
                    v += __shfl_xor_sync(0xFFFFFFFFu, v, 4);
                    v += __shfl_xor_sync(0xFFFFFFFFu, v, 8);
                    v += __shfl_xor_sync(0xFFFFFFFFu, v, 16);
                    if (lane < 4) {
                        int j = j0 + warp_n * 32 + ni * 8 + lane * 2 + cc;
                        g_selfpart2[(size_t)j * 64 + ti * 2 + warp_m] = v;
                    }
                }
            }
        }
    }
}

// ---------------------------------------------------------------------------
// 3) gamma_2 path: colnorm + K-split Gram
// ---------------------------------------------------------------------------
__global__ void colnorm_part_kernel() {
    int b = blockIdx.x, t = threadIdx.x;
    float s = 0.f;
    int r0 = b * 32;
    for (int r = 0; r < 32; r++) {
        float v = g_esa[(size_t)(r0 + r) * DIM + t];
        s += v * v;
    }
    g_c2part[b * DIM + t] = s;
}
__global__ void colnorm_reduce_kernel() {
    int t = threadIdx.x;
    float s = 0.f;
    for (int b = 0; b < 128; b++) s += g_c2part[b * DIM + t];
    g_c2[t] = s;
}
__global__ __launch_bounds__(256)
void d2_part_kernel() {
    __shared__ float Ei[64][32];
    __shared__ float Ej[64][32];
    const int tx = threadIdx.x & 15, ty = threadIdx.x >> 4;
    const int i0 = blockIdx.y * 32, j0 = blockIdx.x * 32;
    const int k0 = blockIdx.z * 512;
    float a00 = 0, a01 = 0, a10 = 0, a11 = 0;
    for (int kc = k0; kc < k0 + 512; kc += 64) {
        #pragma unroll
        for (int r = 0; r < 8; r++) {
            int idx = threadIdx.x + r * 256;
            int kk = idx >> 5, col = idx & 31;
            Ei[kk][col] = g_esa[(size_t)(kc + kk) * DIM + i0 + col];
            Ej[kk][col] = g_esa[(size_t)(kc + kk) * DIM + j0 + col];
        }
        __syncthreads();
        #pragma unroll
        for (int kk = 0; kk < 64; kk++) {
            float xa = Ei[kk][ty], xb = Ei[kk][ty + 16];
            float ya = Ej[kk][tx], yb = Ej[kk][tx + 16];
            a00 += xa * ya; a01 += xa * yb; a10 += xb * ya; a11 += xb * yb;
        }
        __syncthreads();
    }
    float* P = g_D2p + (size_t)blockIdx.z * DIM * DIM;
    P[(i0 + ty) * DIM + j0 + tx]           = a00;
    P[(i0 + ty) * DIM + j0 + tx + 16]      = a01;
    P[(i0 + ty + 16) * DIM + j0 + tx]      = a10;
    P[(i0 + ty + 16) * DIM + j0 + tx + 16] = a11;
}
__global__ void d2_final_kernel() {
    int i = blockIdx.x, j = threadIdx.x;
    float s = 0.f;
    #pragma unroll
    for (int z = 0; z < 8; z++) s += g_D2p[(size_t)z * DIM * DIM + i * DIM + j];
    g_D2[i * DIM + j] = (g_c2[i] + g_c2[j] - 2.f * s) * (1.f / 4096.f);
}

// ---------------------------------------------------------------------------
// 4a) D2 median + gamma_2: one single-block kernel (all 4 radix passes)
// ---------------------------------------------------------------------------
__global__ __launch_bounds__(1024)
void d2_median_kernel() {
    __shared__ unsigned hist[256];
    __shared__ unsigned s[256];
    __shared__ unsigned sh_prefix, sh_k;
    int t = threadIdx.x;
    if (t == 0) { sh_prefix = 0u; sh_k = (DIM * DIM - 1) / 2; }
    __syncthreads();
    #pragma unroll
    for (int pass = 0; pass < 4; pass++) {
        if (t < 256) hist[t] = 0u;
        __syncthreads();
        int shift = 24 - pass * 8;
        unsigned prefix = sh_prefix;
        for (int i = t; i < DIM * DIM; i += 1024) {
            unsigned u = f2u_mono(g_D2[i]);
            bool ok = (pass == 0) || ((u >> (shift + 8)) == prefix);
            if (ok) atomicAdd(&hist[(u >> shift) & 0xFFu], 1u);
        }
        __syncthreads();
        unsigned kcur = sh_k;
        if (t < 256) s[t] = hist[t];
        __syncthreads();
        for (int off = 1; off < 256; off <<= 1) {
            unsigned v = (t < 256 && t >= off) ? s[t - off] : 0u;
            __syncthreads();
            if (t < 256) s[t] += v;
            __syncthreads();
        }
        if (t < 256) {
            unsigned c = hist[t];
            unsigned incl = s[t], excl = incl - c;
            if (kcur >= excl && kcur < incl) {
                sh_k = kcur - excl;
                sh_prefix = (prefix << 8) | (unsigned)t;
            }
        }
        __syncthreads();
    }
    if (t == 0) {
        unsigned u = sh_prefix;
        unsigned bits = (u & 0x80000000u) ? (u ^ 0x80000000u) : ~u;
        g_median[1] = __uint_as_float(bits);
        g_gamma[1]  = 1.0f / (__uint_as_float(bits) + EPS);
    }
}

// ---------------------------------------------------------------------------
// 4b) D median: scan-free chained hist passes.
//     Each block derives the prefix by chaining scans of g_hist4[0..pass-1].
// ---------------------------------------------------------------------------
__device__ __forceinline__ void chain_prefix(int npass, unsigned& prefix_out,
                                             unsigned& k_out,
                                             unsigned* s, unsigned* sh2) {
    // sh2[0] = prefix, sh2[1] = k (shared); 256 threads
    int t = threadIdx.x;
    if (t == 0) { sh2[0] = 0u; sh2[1] = K_TARGET; }
    __syncthreads();
    for (int q = 0; q < npass; q++) {
        unsigned c = g_hist4[q * 256 + t];
        unsigned kcur = sh2[1];
        unsigned pfx  = sh2[0];
        __syncthreads();
        s[t] = c;
        __syncthreads();
        for (int off = 1; off < 256; off <<= 1) {
            unsigned v = (t >= off) ? s[t - off] : 0u;
            __syncthreads();
            s[t] += v;
            __syncthreads();
        }
        unsigned incl = s[t], excl = incl - c;
        if (kcur >= excl && kcur < incl) {
            sh2[1] = kcur - excl;
            sh2[0] = (pfx << 8) | (unsigned)t;
        }
        __syncthreads();
    }
    prefix_out = sh2[0];
    k_out = sh2[1];
}

__global__ __launch_bounds__(256)
void select_hist_chain(const float* __restrict__ data, unsigned n4, int pass) {
    __shared__ unsigned s[256];
    __shared__ unsigned sh2[2];
    __shared__ unsigned hloc[256];
    unsigned prefix, kdummy;
    chain_prefix(pass, prefix, kdummy, s, sh2);

    hloc[threadIdx.x] = 0u;
    __syncthreads();
    int shift = 24 - pass * 8;
    unsigned stride = gridDim.x * blockDim.x;
    int lane = threadIdx.x & 31;
    const float4* d4 = (const float4*)data;
    for (unsigned base = blockIdx.x * blockDim.x; base < n4; base += stride) {
        unsigned i = base + threadIdx.x;
        float4 v = make_float4(0.f, 0.f, 0.f, 0.f);
        bool valid = (i < n4);
        if (valid) v = d4[i];
        float vals[4] = {v.x, v.y, v.z, v.w};
        #pragma unroll
        for (int e = 0; e < 4; e++) {
            unsigned bucket = 0xFFFFFFFFu;
            if (valid) {
                unsigned u = f2u_mono(vals[e]);
                if ((u >> (shift + 8)) == prefix) bucket = (u >> shift) & 0xFFu;
            }
            unsigned m = __match_any_sync(0xFFFFFFFFu, bucket);
            if (bucket != 0xFFFFFFFFu && lane == __ffs(m) - 1)
                atomicAdd(&hloc[bucket], (unsigned)__popc(m));
        }
    }
    __syncthreads();
    if (hloc[threadIdx.x])
        atomicAdd(&g_hist4[pass * 256 + threadIdx.x], hloc[threadIdx.x]);
}

__global__ __launch_bounds__(256)
void select_finalize_chain() {
    __shared__ unsigned s[256];
    __shared__ unsigned sh2[2];
    unsigned prefix, kdummy;
    chain_prefix(4, prefix, kdummy, s, sh2);
    if (threadIdx.x == 0) {
        unsigned bits = (prefix & 0x80000000u) ? (prefix ^ 0x80000000u) : ~prefix;
        g_median[0] = __uint_as_float(bits);
        g_gamma[0]  = 1.0f / (__uint_as_float(bits) + EPS);
    }
}

// ---------------------------------------------------------------------------
// 5) Row means of exp over stored D (agent-expert pass)
// ---------------------------------------------------------------------------
__global__ __launch_bounds__(256)
void rowsum_kernel(const float* __restrict__ D) {
    int i = blockIdx.x, t = threadIdx.x;
    float g1 = g_gamma[0], g2 = g_gamma[1];
    const float4* row = (const float4*)(D + (size_t)i * N);
    float s = 0.f;
    #pragma unroll 4
    for (int j = t; j < N / 4; j += 256) {
        float4 v = row[j];
        s += __expf(-g1 * v.x) + __expf(-g1 * v.y) + __expf(-g1 * v.z) + __expf(-g1 * v.w)
           + __expf(-g2 * v.x) + __expf(-g2 * v.y) + __expf(-g2 * v.z) + __expf(-g2 * v.w);
    }
    __shared__ float sh[256];
    sh[t] = s;
    __syncthreads();
    #pragma unroll
    for (int k = 128; k > 0; k >>= 1) {
        if (t < k) sh[t] += sh[t + k];
        __syncthreads();
    }
    if (t == 0) g_sim[i] = sh[0] * (1.0f / (float)N);
}

// ---------------------------------------------------------------------------
// 6) final: out[i] = g_sim[i] - mean of valid self partials
// ---------------------------------------------------------------------------
__global__ void self_final_kernel(float* __restrict__ out) {
    int i = blockIdx.x * blockDim.x + threadIdx.x;
    int t = i >> 7;
    const float* rp = g_selfpart  + (size_t)i * 128;
    const float* cp = g_selfpart2 + (size_t)i * 64;
    float s = 0.f;
    for (int b = 4 * t; b < 128; b++) s += rp[b];
    for (int b = 0; b < 2 * t; b++)  s += cp[b];
    out[i] = g_sim[i] - s * (1.0f / (float)N);
}

// ---------------------------------------------------------------------------
// Host orchestration (graph-capturable)
// ---------------------------------------------------------------------------
extern "C" void kernel_launch(void* const* d_in, const int* in_sizes, int n_in,
                              void* d_out, int out_size) {
    const float* state   = (const float*)d_in[0];
    const float* action  = (const float*)d_in[1];
    const float* estate  = (const float*)d_in[2];
    const float* eaction = (const float*)d_in[3];
    float* out = (float*)d_out;

    float *p_sa, *p_esa, *p_x2, *p_y2, *p_D;
    __nv_bfloat16 *p_P, *p_Q, *p_R;
    cudaGetSymbolAddress((void**)&p_sa,  g_sa);
    cudaGetSymbolAddress((void**)&p_esa, g_esa);
    cudaGetSymbolAddress((void**)&p_x2,  g_x2);
    cudaGetSymbolAddress((void**)&p_y2,  g_y2);
    cudaGetSymbolAddress((void**)&p_D,   g_D);
    cudaGetSymbolAddress((void**)&p_P,   g_P);
    cudaGetSymbolAddress((void**)&p_Q,   g_Q);
    cudaGetSymbolAddress((void**)&p_R,   g_R);

    cudaFuncSetAttribute(hmma_dist_gemm<0>,
                         cudaFuncAttributeMaxDynamicSharedMemorySize, GM_SMEM);
    cudaFuncSetAttribute(hmma_dist_gemm<1>,
                         cudaFuncAttributeMaxDynamicSharedMemorySize, GM_SMEM);

    // 1) concat + norms + bf16 splits (also zeroes g_hist4)
    prep_kernel<<<N, 256>>>(state,  action,  p_sa,  p_x2, p_P, 1, p_Q);
    prep_kernel<<<N, 256>>>(estate, eaction, p_esa, p_y2, p_R, 0, nullptr);

    // 2) D_agent_expert + fused MSB histogram -> g_hist4[0]
    dim3 ggrid(N / 128, N / 128);
    hmma_dist_gemm<0><<<ggrid, 256, GM_SMEM>>>(p_P, p_R, p_x2, p_y2, p_D);

    // 3) gamma_2 matrix + single-launch median/gamma_2
    colnorm_part_kernel<<<128, 256>>>();
    colnorm_reduce_kernel<<<1, 256>>>();
    d2_part_kernel<<<dim3(8, 8, 8), 256>>>();
    d2_final_kernel<<<DIM, DIM>>>();
    d2_median_kernel<<<1, 1024>>>();

    // 4) D median passes 1..3 (pass 0 fused) + finalize/gamma_1
    {
        unsigned n4 = ((unsigned)N * (unsigned)N) / 4u;
        unsigned blocks = 2048u;
        for (int p = 1; p <= 3; p++)
            select_hist_chain<<<blocks, 256>>>(p_D, n4, p);
        select_finalize_chain<<<1, 256>>>();
    }

    // 5) agent-expert similarity means from stored D
    rowsum_kernel<<<N, 256>>>(p_D);

    // 6) self-distance GEMM, triangular, fused row+col sums
    hmma_dist_gemm<1><<<NTRI, 256, GM_SMEM>>>(p_P, p_Q, p_x2, p_x2, nullptr);
    self_final_kernel<<<N / 256, 256>>>(out);
}

// round 10
// speedup vs baseline: 1.7755x; 1.0057x over previous
#include <cuda_runtime.h>
#include <cuda_bf16.h>
#include <cstdint>
#include <cmath>

// ---------------------------------------------------------------------------
// Shapes: n1 = n2 = 4096, s = 192, a = 64, d = 256. Split-GEMM K = 768.
// ---------------------------------------------------------------------------
#define N      4096
#define DIM    256
#define SDIM   192
#define ADIM   64
#define KSPLIT 768
#define EPS    1e-8f

// ---------------------------------------------------------------------------
// Scratch (device globals — allocations forbidden)
// ---------------------------------------------------------------------------
__device__ __align__(256) float g_sa [N * DIM];
__device__ __align__(256) float g_esa[N * DIM];
__device__ __align__(256) float g_x2 [N];
__device__ __align__(256) float g_y2 [N];
__device__ __align__(256) float g_D  [(size_t)N * N];        // 64 MB
__device__ __align__(256) float g_D2 [DIM * DIM];
__device__ __align__(256) float g_D2p[8 * DIM * DIM];
__device__ __align__(256) float g_sim[N];
__device__ __align__(256) float g_selfpart [(size_t)N * 128]; // row-sum slots
__device__ __align__(256) float g_selfpart2[(size_t)N * 64];  // col-sum slots
__device__ __align__(256) __nv_bfloat16 g_P[(size_t)N * KSPLIT]; // sa  [hi|hi|lo]
__device__ __align__(256) __nv_bfloat16 g_Q[(size_t)N * KSPLIT]; // sa  [hi|lo|hi]
__device__ __align__(256) __nv_bfloat16 g_R[(size_t)N * KSPLIT]; // esa [hi|lo|hi]
__device__ unsigned g_hist4[4 * 256];  // per-pass histograms (prep zeroes)
__device__ float    g_median[2];
__device__ float    g_gamma[2];

#define K_TARGET 8388607u   // (N*N - 1) / 2

// ---------------------------------------------------------------------------
// helpers
// ---------------------------------------------------------------------------
__device__ __forceinline__ uint32_t smem_u32(const void* p) {
    uint32_t a;
    asm("{ .reg .u64 t; cvta.to.shared.u64 t, %1; cvt.u32.u64 %0, t; }"
        : "=r"(a) : "l"(p));
    return a;
}
#define SW128B(o) ((o) ^ (((o) >> 3) & 0x70))

__device__ __forceinline__ void cp_async16(uint32_t sdst, const void* gsrc) {
    asm volatile("cp.async.cg.shared.global [%0], [%1], 16;"
                 :: "r"(sdst), "l"(gsrc) : "memory");
}
__device__ __forceinline__ void cp_commit() {
    asm volatile("cp.async.commit_group;" ::: "memory");
}
__device__ __forceinline__ void ldmx4(uint32_t& r0, uint32_t& r1,
                                      uint32_t& r2, uint32_t& r3, uint32_t addr) {
    asm volatile("ldmatrix.sync.aligned.m8n8.x4.shared.b16 {%0,%1,%2,%3}, [%4];"
                 : "=r"(r0), "=r"(r1), "=r"(r2), "=r"(r3) : "r"(addr));
}
__device__ __forceinline__ void mma_bf16(float& c0, float& c1, float& c2, float& c3,
                                         uint32_t a0, uint32_t a1, uint32_t a2, uint32_t a3,
                                         uint32_t b0, uint32_t b1) {
    asm volatile(
        "mma.sync.aligned.m16n8k16.row.col.f32.bf16.bf16.f32 "
        "{%0,%1,%2,%3}, {%4,%5,%6,%7}, {%8,%9}, {%0,%1,%2,%3};"
        : "+f"(c0), "+f"(c1), "+f"(c2), "+f"(c3)
        : "r"(a0), "r"(a1), "r"(a2), "r"(a3), "r"(b0), "r"(b1));
}
__device__ __forceinline__ unsigned f2u_mono(float f) {
    unsigned b = __float_as_uint(f);
    return (b & 0x80000000u) ? ~b : (b | 0x80000000u);
}

// ---------------------------------------------------------------------------
// 1) concat + norm + bf16 hi/lo splits, fused. Also zeroes g_hist4.
// ---------------------------------------------------------------------------
__global__ void prep_kernel(const float* __restrict__ st,
                            const float* __restrict__ ac,
                            float* __restrict__ cat, float* __restrict__ nrm,
                            __nv_bfloat16* __restrict__ dst0, int phl0,
                            __nv_bfloat16* __restrict__ dst1) {
    int row = blockIdx.x, t = threadIdx.x;
    if (blockIdx.x < 4) g_hist4[blockIdx.x * 256 + t] = 0u;
    float v = (t < SDIM) ? st[row * SDIM + t] : ac[row * ADIM + (t - SDIM)];
    cat[row * DIM + t] = v;
    __nv_bfloat16 hi = __float2bfloat16(v);
    __nv_bfloat16 lo = __float2bfloat16(v - __bfloat162float(hi));
    size_t base = (size_t)row * KSPLIT + t;
    dst0[base]       = hi;
    dst0[base + 256] = phl0 ? hi : lo;
    dst0[base + 512] = phl0 ? lo : hi;
    if (dst1) { dst1[base] = hi; dst1[base + 256] = lo; dst1[base + 512] = hi; }

    __shared__ float sh[256];
    sh[t] = v * v;
    __syncthreads();
    #pragma unroll
    for (int s = 128; s > 0; s >>= 1) {
        if (t < s) sh[t] += sh[t + s];
        __syncthreads();
    }
    if (t == 0) nrm[row] = sh[0];
}

// ---------------------------------------------------------------------------
// 2) HMMA distance GEMM — 128x128 CTA tile, 8 warps (2x4) of 64x32, BK=64,
//    3-stage cp.async pipeline, SW128 smem, K = 768, 2 CTAs/SM.
//    MODE 0: full grid; store D + fused MSB histogram -> g_hist4[0].
//    MODE 1: triangular grid (528 tiles); fused self row+col exp-sums, no D.
// ---------------------------------------------------------------------------
#define BK        64
#define TILE_B    (128 * BK * 2)          // 16 KB per operand per stage
#define STG       (2 * TILE_B)            // 32 KB per stage (A+B)
#define GM_SMEM   (3 * STG)               // 96 KB
#define NCHUNK    12
#define NTILE     32
#define NTRI      (NTILE * (NTILE + 1) / 2)

__device__ __forceinline__ void gemm_issue_stage(
    const __nv_bfloat16* __restrict__ A, const __nv_bfloat16* __restrict__ B,
    int i0, int j0, int c, uint32_t sA, uint32_t sB, int tid)
{
    const __nv_bfloat16* Ap = A + (size_t)i0 * KSPLIT + c * BK;
    const __nv_bfloat16* Bp = B + (size_t)j0 * KSPLIT + c * BK;
    #pragma unroll
    for (int q = 0; q < 4; q++) {
        int idx = tid + q * 256;
        int row = idx >> 3, seg = idx & 7;
        cp_async16(sA + SW128B(row * 128 + seg * 16),
                   Ap + (size_t)row * KSPLIT + seg * 8);
    }
    #pragma unroll
    for (int q = 0; q < 4; q++) {
        int idx = tid + q * 256;
        int row = idx >> 3, seg = idx & 7;
        cp_async16(sB + SW128B(row * 128 + seg * 16),
                   Bp + (size_t)row * KSPLIT + seg * 8);
    }
    cp_commit();
}

template <int MODE>
__global__ __launch_bounds__(256, 2)
void hmma_dist_gemm(const __nv_bfloat16* __restrict__ A,
                    const __nv_bfloat16* __restrict__ B,
                    const float* __restrict__ x2,
                    const float* __restrict__ y2,
                    float* __restrict__ D)
{
    extern __shared__ char smem[];
    const uint32_t sb = smem_u32(smem);
    const int tid = threadIdx.x;
    const int wid = tid >> 5, lane = tid & 31;
    const int warp_m = wid >> 2, warp_n = wid & 3;   // 2 x 4 warps

    int ti, tj;
    if (MODE == 1) {
        int bid = blockIdx.x;
        ti = (int)(32.5f - sqrtf(32.5f * 32.5f - 2.0f * (float)bid));
        while (NTILE * ti - ti * (ti - 1) / 2 > bid) ti--;
        while (NTILE * (ti + 1) - (ti + 1) * ti / 2 <= bid) ti++;
        tj = ti + (bid - (NTILE * ti - ti * (ti - 1) / 2));
    } else {
        ti = blockIdx.y;
        tj = blockIdx.x;
    }
    const int i0 = ti * 128;
    const int j0 = tj * 128;

    uint32_t sA[3] = { sb,           sb + STG,           sb + 2 * STG };
    uint32_t sB[3] = { sb + TILE_B,  sb + STG + TILE_B,  sb + 2 * STG + TILE_B };

    float acc[4][4][4];
    #pragma unroll
    for (int mi = 0; mi < 4; mi++)
        #pragma unroll
        for (int ni = 0; ni < 4; ni++)
            #pragma unroll
            for (int e = 0; e < 4; e++) acc[mi][ni][e] = 0.f;

    gemm_issue_stage(A, B, i0, j0, 0, sA[0], sB[0], tid);
    gemm_issue_stage(A, B, i0, j0, 1, sA[1], sB[1], tid);
    gemm_issue_stage(A, B, i0, j0, 2, sA[2], sB[2], tid);

    const int a_row = (lane & 15);
    const int a_col = (lane & 16) ? 8 : 0;
    const int b_row = (lane & 7) + ((lane & 16) >> 1);
    const int b_col = (lane & 8) ? 8 : 0;

    for (int c = 0; c < NCHUNK; c++) {
        if (c < 10)      asm volatile("cp.async.wait_group 2;" ::: "memory");
        else if (c < 11) asm volatile("cp.async.wait_group 1;" ::: "memory");
        else             asm volatile("cp.async.wait_group 0;" ::: "memory");
        __syncthreads();

        int buf = c % 3;
        uint32_t cA = sA[buf], cB = sB[buf];
        #pragma unroll
        for (int ks = 0; ks < BK / 16; ks++) {
            int k0 = ks * 16;
            uint32_t a[4][4], b[2][4];
            #pragma unroll
            for (int mi = 0; mi < 4; mi++) {
                int row = warp_m * 64 + mi * 16 + a_row;
                ldmx4(a[mi][0], a[mi][1], a[mi][2], a[mi][3],
                      cA + SW128B(row * 128 + (k0 + a_col) * 2));
            }
            #pragma unroll
            for (int nb = 0; nb < 2; nb++) {
                int row = warp_n * 32 + nb * 16 + b_row;
                ldmx4(b[nb][0], b[nb][1], b[nb][2], b[nb][3],
                      cB + SW128B(row * 128 + (k0 + b_col) * 2));
            }
            #pragma unroll
            for (int mi = 0; mi < 4; mi++)
                #pragma unroll
                for (int ni = 0; ni < 4; ni++)
                    mma_bf16(acc[mi][ni][0], acc[mi][ni][1],
                             acc[mi][ni][2], acc[mi][ni][3],
                             a[mi][0], a[mi][1], a[mi][2], a[mi][3],
                             b[ni >> 1][(ni & 1) * 2], b[ni >> 1][(ni & 1) * 2 + 1]);
        }
        __syncthreads();
        if (c + 3 < NCHUNK)
            gemm_issue_stage(A, B, i0, j0, c + 3, sA[buf], sB[buf], tid);
    }

    const int qrow = lane >> 2;
    const int qcol = (lane & 3) * 2;

    if (MODE == 0) {
        unsigned* hsh = (unsigned*)smem;
        hsh[tid] = 0u;
        __syncthreads();
        unsigned lastb = 0xFFFFFFFFu, cnt = 0;

        #pragma unroll
        for (int mi = 0; mi < 4; mi++) {
            int i_lo = i0 + warp_m * 64 + mi * 16 + qrow;
            int i_hi = i_lo + 8;
            float xlo = x2[i_lo], xhi = x2[i_hi];
            #pragma unroll
            for (int ni = 0; ni < 4; ni++) {
                int j = j0 + warp_n * 32 + ni * 8 + qcol;
                float yj0 = y2[j], yj1 = y2[j + 1];
                float2 vlo, vhi;
                vlo.x = (xlo + yj0 - 2.f * acc[mi][ni][0]) * 0.00390625f;
                vlo.y = (xlo + yj1 - 2.f * acc[mi][ni][1]) * 0.00390625f;
                vhi.x = (xhi + yj0 - 2.f * acc[mi][ni][2]) * 0.00390625f;
                vhi.y = (xhi + yj1 - 2.f * acc[mi][ni][3]) * 0.00390625f;
                *(float2*)(D + (size_t)i_lo * N + j) = vlo;
                *(float2*)(D + (size_t)i_hi * N + j) = vhi;
                float vs[4] = {vlo.x, vlo.y, vhi.x, vhi.y};
                #pragma unroll
                for (int e = 0; e < 4; e++) {
                    unsigned bk = f2u_mono(vs[e]) >> 24;
                    if (bk == lastb) cnt++;
                    else {
                        if (cnt) atomicAdd(&hsh[lastb], cnt);
                        lastb = bk; cnt = 1;
                    }
                }
            }
        }
        if (cnt) atomicAdd(&hsh[lastb], cnt);
        __syncthreads();
        if (hsh[tid]) atomicAdd(&g_hist4[tid], hsh[tid]);
    } else {
        float g1 = g_gamma[0], g2 = g_gamma[1];
        float csum[4][2];
        #pragma unroll
        for (int ni = 0; ni < 4; ni++) { csum[ni][0] = 0.f; csum[ni][1] = 0.f; }

        #pragma unroll
        for (int mi = 0; mi < 4; mi++) {
            int i_lo = i0 + warp_m * 64 + mi * 16 + qrow;
            int i_hi = i_lo + 8;
            float xlo = x2[i_lo], xhi = x2[i_hi];
            float slo = 0.f, shi = 0.f;
            #pragma unroll
            for (int ni = 0; ni < 4; ni++) {
                int j = j0 + warp_n * 32 + ni * 8 + qcol;
                float yj0 = y2[j], yj1 = y2[j + 1];
                float d0 = (xlo + yj0 - 2.f * acc[mi][ni][0]) * 0.00390625f;
                float d1 = (xlo + yj1 - 2.f * acc[mi][ni][1]) * 0.00390625f;
                float d2v = (xhi + yj0 - 2.f * acc[mi][ni][2]) * 0.00390625f;
                float d3 = (xhi + yj1 - 2.f * acc[mi][ni][3]) * 0.00390625f;
                float e0 = __expf(-g1 * d0)  + __expf(-g2 * d0);
                float e1 = __expf(-g1 * d1)  + __expf(-g2 * d1);
                float e2 = __expf(-g1 * d2v) + __expf(-g2 * d2v);
                float e3 = __expf(-g1 * d3)  + __expf(-g2 * d3);
                slo += e0 + e1;
                shi += e2 + e3;
                csum[ni][0] += e0 + e2;
                csum[ni][1] += e1 + e3;
            }
            slo += __shfl_xor_sync(0xFFFFFFFFu, slo, 1);
            slo += __shfl_xor_sync(0xFFFFFFFFu, slo, 2);
            shi += __shfl_xor_sync(0xFFFFFFFFu, shi, 1);
            shi += __shfl_xor_sync(0xFFFFFFFFu, shi, 2);
            if ((lane & 3) == 0) {
                int col = tj * 4 + warp_n;
                g_selfpart[(size_t)i_lo * 128 + col] = slo;
                g_selfpart[(size_t)i_hi * 128 + col] = shi;
            }
        }
        if (ti != tj) {
            #pragma unroll
            for (int ni = 0; ni < 4; ni++) {
                #pragma unroll
                for (int cc = 0; cc < 2; cc++) {
                    float v = csum[ni][cc];
                    v += __shfl_xor_sync(0xFFFFFFFFu, v, 4);
                    v += __shfl_xor_sync(0xFFFFFFFFu, v, 8);
                    v += __shfl_xor_sync(0xFFFFFFFFu, v, 16);
                    if (lane < 4) {
                        int j = j0 + warp_n * 32 + ni * 8 + lane * 2 + cc;
                        g_selfpart2[(size_t)j * 64 + ti * 2 + warp_m] = v;
                    }
                }
            }
        }
    }
}

// ---------------------------------------------------------------------------
// 3) gamma_2 path: K-split Gram (c2 comes from the Gram diagonal)
// ---------------------------------------------------------------------------
__global__ __launch_bounds__(256)
void d2_part_kernel() {
    __shared__ float Ei[64][32];
    __shared__ float Ej[64][32];
    const int tx = threadIdx.x & 15, ty = threadIdx.x >> 4;
    const int i0 = blockIdx.y * 32, j0 = blockIdx.x * 32;
    const int k0 = blockIdx.z * 512;
    float a00 = 0, a01 = 0, a10 = 0, a11 = 0;
    for (int kc = k0; kc < k0 + 512; kc += 64) {
        #pragma unroll
        for (int r = 0; r < 8; r++) {
            int idx = threadIdx.x + r * 256;
            int kk = idx >> 5, col = idx & 31;
            Ei[kk][col] = g_esa[(size_t)(kc + kk) * DIM + i0 + col];
            Ej[kk][col] = g_esa[(size_t)(kc + kk) * DIM + j0 + col];
        }
        __syncthreads();
        #pragma unroll
        for (int kk = 0; kk < 64; kk++) {
            float xa = Ei[kk][ty], xb = Ei[kk][ty + 16];
            float ya = Ej[kk][tx], yb = Ej[kk][tx + 16];
            a00 += xa * ya; a01 += xa * yb; a10 += xb * ya; a11 += xb * yb;
        }
        __syncthreads();
    }
    float* P = g_D2p + (size_t)blockIdx.z * DIM * DIM;
    P[(i0 + ty) * DIM + j0 + tx]           = a00;
    P[(i0 + ty) * DIM + j0 + tx + 16]      = a01;
    P[(i0 + ty + 16) * DIM + j0 + tx]      = a10;
    P[(i0 + ty + 16) * DIM + j0 + tx + 16] = a11;
}
__global__ void d2_final_kernel() {
    int i = blockIdx.x, t = threadIdx.x;
    __shared__ float diag[256];
    float dsum = 0.f;
    #pragma unroll
    for (int z = 0; z < 8; z++)
        dsum += g_D2p[(size_t)z * DIM * DIM + t * DIM + t];
    diag[t] = dsum;
    float s = 0.f;
    #pragma unroll
    for (int z = 0; z < 8; z++)
        s += g_D2p[(size_t)z * DIM * DIM + i * DIM + t];
    __syncthreads();
    g_D2[i * DIM + t] = (diag[i] + diag[t] - 2.f * s) * (1.f / 4096.f);
}

// ---------------------------------------------------------------------------
// 4a) D2 median + gamma_2: one single-block kernel (all 4 radix passes)
// ---------------------------------------------------------------------------
__global__ __launch_bounds__(1024)
void d2_median_kernel() {
    __shared__ unsigned hist[256];
    __shared__ unsigned s[256];
    __shared__ unsigned sh_prefix, sh_k;
    int t = threadIdx.x;
    if (t == 0) { sh_prefix = 0u; sh_k = (DIM * DIM - 1) / 2; }
    __syncthreads();
    #pragma unroll
    for (int pass = 0; pass < 4; pass++) {
        if (t < 256) hist[t] = 0u;
        __syncthreads();
        int shift = 24 - pass * 8;
        unsigned prefix = sh_prefix;
        for (int i = t; i < DIM * DIM; i += 1024) {
            unsigned u = f2u_mono(g_D2[i]);
            bool ok = (pass == 0) || ((u >> (shift + 8)) == prefix);
            if (ok) atomicAdd(&hist[(u >> shift) & 0xFFu], 1u);
        }
        __syncthreads();
        unsigned kcur = sh_k;
        if (t < 256) s[t] = hist[t];
        __syncthreads();
        for (int off = 1; off < 256; off <<= 1) {
            unsigned v = (t < 256 && t >= off) ? s[t - off] : 0u;
            __syncthreads();
            if (t < 256) s[t] += v;
            __syncthreads();
        }
        if (t < 256) {
            unsigned c = hist[t];
            unsigned incl = s[t], excl = incl - c;
            if (kcur >= excl && kcur < incl) {
                sh_k = kcur - excl;
                sh_prefix = (prefix << 8) | (unsigned)t;
            }
        }
        __syncthreads();
    }
    if (t == 0) {
        unsigned u = sh_prefix;
        unsigned bits = (u & 0x80000000u) ? (u ^ 0x80000000u) : ~u;
        g_median[1] = __uint_as_float(bits);
        g_gamma[1]  = 1.0f / (__uint_as_float(bits) + EPS);
    }
}

// ---------------------------------------------------------------------------
// 4b) D median: scan-free chained hist passes.
// ---------------------------------------------------------------------------
__device__ __forceinline__ void chain_prefix(int npass, unsigned& prefix_out,
                                             unsigned& k_out,
                                             unsigned* s, unsigned* sh2) {
    int t = threadIdx.x;
    if (t == 0) { sh2[0] = 0u; sh2[1] = K_TARGET; }
    __syncthreads();
    for (int q = 0; q < npass; q++) {
        unsigned c = g_hist4[q * 256 + t];
        unsigned kcur = sh2[1];
        unsigned pfx  = sh2[0];
        __syncthreads();
        s[t] = c;
        __syncthreads();
        for (int off = 1; off < 256; off <<= 1) {
            unsigned v = (t >= off) ? s[t - off] : 0u;
            __syncthreads();
            s[t] += v;
            __syncthreads();
        }
        unsigned incl = s[t], excl = incl - c;
        if (kcur >= excl && kcur < incl) {
            sh2[1] = kcur - excl;
            sh2[0] = (pfx << 8) | (unsigned)t;
        }
        __syncthreads();
    }
    prefix_out = sh2[0];
    k_out = sh2[1];
}

__global__ __launch_bounds__(256)
void select_hist_chain(const float* __restrict__ data, unsigned n4, int pass) {
    __shared__ unsigned s[256];
    __shared__ unsigned sh2[2];
    __shared__ unsigned hloc[256];
    unsigned prefix, kdummy;
    chain_prefix(pass, prefix, kdummy, s, sh2);

    hloc[threadIdx.x] = 0u;
    __syncthreads();
    int shift = 24 - pass * 8;
    unsigned stride = gridDim.x * blockDim.x;
    int lane = threadIdx.x & 31;
    const float4* d4 = (const float4*)data;
    for (unsigned base = blockIdx.x * blockDim.x; base < n4; base += stride) {
        unsigned i = base + threadIdx.x;
        float4 v = make_float4(0.f, 0.f, 0.f, 0.f);
        bool valid = (i < n4);
        if (valid) v = d4[i];
        float vals[4] = {v.x, v.y, v.z, v.w};
        #pragma unroll
        for (int e = 0; e < 4; e++) {
            unsigned bucket = 0xFFFFFFFFu;
            if (valid) {
                unsigned u = f2u_mono(vals[e]);
                if ((u >> (shift + 8)) == prefix) bucket = (u >> shift) & 0xFFu;
            }
            unsigned m = __match_any_sync(0xFFFFFFFFu, bucket);
            if (bucket != 0xFFFFFFFFu && lane == __ffs(m) - 1)
                atomicAdd(&hloc[bucket], (unsigned)__popc(m));
        }
    }
    __syncthreads();
    if (hloc[threadIdx.x])
        atomicAdd(&g_hist4[pass * 256 + threadIdx.x], hloc[threadIdx.x]);
}

__global__ __launch_bounds__(256)
void select_finalize_chain() {
    __shared__ unsigned s[256];
    __shared__ unsigned sh2[2];
    unsigned prefix, kdummy;
    chain_prefix(4, prefix, kdummy, s, sh2);
    if (threadIdx.x == 0) {
        unsigned bits = (prefix & 0x80000000u) ? (prefix ^ 0x80000000u) : ~prefix;
        g_median[0] = __uint_as_float(bits);
        g_gamma[0]  = 1.0f / (__uint_as_float(bits) + EPS);
    }
}

// ---------------------------------------------------------------------------
// 5) Row means of exp over stored D (agent-expert pass)
// ---------------------------------------------------------------------------
__global__ __launch_bounds__(256)
void rowsum_kernel(const float* __restrict__ D) {
    int i = blockIdx.x, t = threadIdx.x;
    float g1 = g_gamma[0], g2 = g_gamma[1];
    const float4* row = (const float4*)(D + (size_t)i * N);
    float s = 0.f;
    #pragma unroll 4
    for (int j = t; j < N / 4; j += 256) {
        float4 v = row[j];
        s += __expf(-g1 * v.x) + __expf(-g1 * v.y) + __expf(-g1 * v.z) + __expf(-g1 * v.w)
           + __expf(-g2 * v.x) + __expf(-g2 * v.y) + __expf(-g2 * v.z) + __expf(-g2 * v.w);
    }
    __shared__ float sh[256];
    sh[t] = s;
    __syncthreads();
    #pragma unroll
    for (int k = 128; k > 0; k >>= 1) {
        if (t < k) sh[t] += sh[t + k];
        __syncthreads();
    }
    if (t == 0) g_sim[i] = sh[0] * (1.0f / (float)N);
}

// ---------------------------------------------------------------------------
// 6) final: out[i] = g_sim[i] - mean of valid self partials
// ---------------------------------------------------------------------------
__global__ void self_final_kernel(float* __restrict__ out) {
    int i = blockIdx.x * blockDim.x + threadIdx.x;
    int t = i >> 7;
    const float* rp = g_selfpart  + (size_t)i * 128;
    const float* cp = g_selfpart2 + (size_t)i * 64;
    float s = 0.f;
    for (int b = 4 * t; b < 128; b++) s += rp[b];
    for (int b = 0; b < 2 * t; b++)  s += cp[b];
    out[i] = g_sim[i] - s * (1.0f / (float)N);
}

// ---------------------------------------------------------------------------
// Host orchestration (graph-capturable)
// ---------------------------------------------------------------------------
extern "C" void kernel_launch(void* const* d_in, const int* in_sizes, int n_in,
                              void* d_out, int out_size) {
    const float* state   = (const float*)d_in[0];
    const float* action  = (const float*)d_in[1];
    const float* estate  = (const float*)d_in[2];
    const float* eaction = (const float*)d_in[3];
    float* out = (float*)d_out;

    float *p_sa, *p_esa, *p_x2, *p_y2, *p_D;
    __nv_bfloat16 *p_P, *p_Q, *p_R;
    cudaGetSymbolAddress((void**)&p_sa,  g_sa);
    cudaGetSymbolAddress((void**)&p_esa, g_esa);
    cudaGetSymbolAddress((void**)&p_x2,  g_x2);
    cudaGetSymbolAddress((void**)&p_y2,  g_y2);
    cudaGetSymbolAddress((void**)&p_D,   g_D);
    cudaGetSymbolAddress((void**)&p_P,   g_P);
    cudaGetSymbolAddress((void**)&p_Q,   g_Q);
    cudaGetSymbolAddress((void**)&p_R,   g_R);

    cudaFuncSetAttribute(hmma_dist_gemm<0>,
                         cudaFuncAttributeMaxDynamicSharedMemorySize, GM_SMEM);
    cudaFuncSetAttribute(hmma_dist_gemm<1>,
                         cudaFuncAttributeMaxDynamicSharedMemorySize, GM_SMEM);

    // 1) concat + norms + bf16 splits (also zeroes g_hist4)
    prep_kernel<<<N, 256>>>(state,  action,  p_sa,  p_x2, p_P, 1, p_Q);
    prep_kernel<<<N, 256>>>(estate, eaction, p_esa, p_y2, p_R, 0, nullptr);

    // 2) D_agent_expert + fused MSB histogram -> g_hist4[0]
    dim3 ggrid(N / 128, N / 128);
    hmma_dist_gemm<0><<<ggrid, 256, GM_SMEM>>>(p_P, p_R, p_x2, p_y2, p_D);

    // 3) gamma_2 matrix (c2 from Gram diagonal) + single-launch median
    d2_part_kernel<<<dim3(8, 8, 8), 256>>>();
    d2_final_kernel<<<DIM, DIM>>>();
    d2_median_kernel<<<1, 1024>>>();

    // 4) D median passes 1..3 (pass 0 fused) + finalize/gamma_1
    {
        unsigned n4 = ((unsigned)N * (unsigned)N) / 4u;
        unsigned blocks = 2048u;
        for (int p = 1; p <= 3; p++)
            select_hist_chain<<<blocks, 256>>>(p_D, n4, p);
        select_finalize_chain<<<1, 256>>>();
    }

    // 5) agent-expert similarity means from stored D
    rowsum_kernel<<<N, 256>>>(p_D);

    // 6) self-distance GEMM, triangular, fused row+col sums
    hmma_dist_gemm<1><<<NTRI, 256, GM_SMEM>>>(p_P, p_Q, p_x2, p_x2, nullptr);
    self_final_kernel<<<N / 256, 256>>>(out);
}